// round 8
// baseline (speedup 1.0000x reference)
#include <cuda_runtime.h>
#include <cuda_bf16.h>
#include <cstdint>

// ---------------------------------------------------------------------------
// MQA, split-bf16 mma.sync. R8: flash QK uses 3 independent accumulators per
// S-fragment (one per split product) -> 6 concurrent MMA chains, merged by
// FADD before softmax. Everything else as R7.
// ---------------------------------------------------------------------------
#define NB     2
#define SEQ    2048
#define HIDDIM 1024
#define NHEAD  16
#define HD     64
#define MTOT   (NB * SEQ)
#define QK_SCALE_LOG2E 0.180336880111120f   // 0.125 * log2(e)

typedef __nv_bfloat16 bf16;

__device__ bf16 g_Xh[MTOT * HIDDIM], g_Xl[MTOT * HIDDIM];
__device__ bf16 g_Wqh[HIDDIM * HIDDIM], g_Wql[HIDDIM * HIDDIM];
__device__ bf16 g_Wkh[HIDDIM * HD],     g_Wkl[HIDDIM * HD];
__device__ bf16 g_Wvh[HIDDIM * HD],     g_Wvl[HIDDIM * HD];
__device__ bf16 g_Woh[HIDDIM * HIDDIM], g_Wol[HIDDIM * HIDDIM];
__device__ bf16 g_Qh[MTOT * HIDDIM], g_Ql[MTOT * HIDDIM];
__device__ bf16 g_Kh[MTOT * HD],     g_Kl[MTOT * HD];
__device__ bf16 g_Vh[MTOT * HD],     g_Vl[MTOT * HD];
__device__ bf16 g_Ah[MTOT * HIDDIM], g_Al[MTOT * HIDDIM];

// ---------------- helpers ----------------
__device__ __forceinline__ uint32_t s2u(const void* p) {
    uint32_t a;
    asm("{ .reg .u64 t; cvta.to.shared.u64 t, %1; cvt.u32.u64 %0, t; }"
        : "=r"(a) : "l"(p));
    return a;
}
__device__ __forceinline__ void cpa16(uint32_t dst, const void* src) {
    asm volatile("cp.async.cg.shared.global [%0], [%1], 16;" :: "r"(dst), "l"(src));
}
#define CP_COMMIT() asm volatile("cp.async.commit_group;" ::: "memory")
#define CP_WAIT(n)  asm volatile("cp.async.wait_group %0;" :: "n"(n) : "memory")

__device__ __forceinline__ void ldm4(uint32_t* r, uint32_t a) {
    asm volatile("ldmatrix.sync.aligned.m8n8.x4.shared.b16 {%0,%1,%2,%3}, [%4];"
        : "=r"(r[0]), "=r"(r[1]), "=r"(r[2]), "=r"(r[3]) : "r"(a));
}
__device__ __forceinline__ void ldm4t(uint32_t* r, uint32_t a) {
    asm volatile("ldmatrix.sync.aligned.m8n8.x4.trans.shared.b16 {%0,%1,%2,%3}, [%4];"
        : "=r"(r[0]), "=r"(r[1]), "=r"(r[2]), "=r"(r[3]) : "r"(a));
}
__device__ __forceinline__ void mmabf(float* d, const uint32_t* a, const uint32_t* b) {
    asm volatile("mma.sync.aligned.m16n8k16.row.col.f32.bf16.bf16.f32 "
        "{%0,%1,%2,%3},{%4,%5,%6,%7},{%8,%9},{%0,%1,%2,%3};"
        : "+f"(d[0]), "+f"(d[1]), "+f"(d[2]), "+f"(d[3])
        : "r"(a[0]), "r"(a[1]), "r"(a[2]), "r"(a[3]), "r"(b[0]), "r"(b[1]));
}
__device__ __forceinline__ void split2pk(float a, float b, uint32_t& hi, uint32_t& lo) {
    __nv_bfloat16 ha = __float2bfloat16_rn(a), hb = __float2bfloat16_rn(b);
    float ra = a - __bfloat162float(ha), rb = b - __bfloat162float(hb);
    __nv_bfloat16 la = __float2bfloat16_rn(ra), lb = __float2bfloat16_rn(rb);
    hi = (uint32_t)__bfloat16_as_ushort(ha) | ((uint32_t)__bfloat16_as_ushort(hb) << 16);
    lo = (uint32_t)__bfloat16_as_ushort(la) | ((uint32_t)__bfloat16_as_ushort(lb) << 16);
}

// ---------------------------------------------------------------------------
// Fused split: all 5 inputs, one launch.
// ---------------------------------------------------------------------------
#define R_X  1048576
#define R_WQ (R_X + 262144)
#define R_WK (R_WQ + 16384)
#define R_WV (R_WK + 16384)
#define R_WO (R_WV + 262144)

__global__ void split_all(const float* __restrict__ x,  const float* __restrict__ wq,
                          const float* __restrict__ wk, const float* __restrict__ wv,
                          const float* __restrict__ wo,
                          bf16* xh, bf16* xl, bf16* qh, bf16* ql, bf16* kh, bf16* kl,
                          bf16* vh, bf16* vl, bf16* oh, bf16* ol)
{
    int i = blockIdx.x * blockDim.x + threadIdx.x;
    const float* in; bf16 *hi, *lo; int j;
    if (i < R_X)       { in = x;  hi = xh; lo = xl; j = i; }
    else if (i < R_WQ) { in = wq; hi = qh; lo = ql; j = i - R_X; }
    else if (i < R_WK) { in = wk; hi = kh; lo = kl; j = i - R_WQ; }
    else if (i < R_WV) { in = wv; hi = vh; lo = vl; j = i - R_WK; }
    else               { in = wo; hi = oh; lo = ol; j = i - R_WV; }
    float4 v = ((const float4*)in)[j];
    uint32_t h0, l0, h1, l1;
    split2pk(v.x, v.y, h0, l0);
    split2pk(v.z, v.w, h1, l1);
    ((uint2*)hi)[j] = make_uint2(h0, h1);
    ((uint2*)lo)[j] = make_uint2(l0, l1);
}

// ---------------------------------------------------------------------------
// GEMM body: C[128 x NTILE] tile of A[M,K]*B[K,N]; cp.async 2-stage.
// ---------------------------------------------------------------------------
template<int NTILE, int EPI>
__device__ __forceinline__
void gemm_body(const bf16* __restrict__ Ah, const bf16* __restrict__ Al,
               const bf16* __restrict__ Bh, const bf16* __restrict__ Bl,
               float* __restrict__ Cf, bf16* __restrict__ Ch, bf16* __restrict__ Cl,
               int N, int K, float scale, int m0, int n0, char* smc)
{
    constexpr int ASZ = 128 * 64;
    constexpr int BSZ = 32 * NTILE * 2;
    constexpr int STG = 2 * ASZ + 2 * BSZ;
    constexpr int RB  = NTILE * 2;
    constexpr int NTT = NTILE / 32;

    const int tid = threadIdx.x, l = tid & 31, wid = tid >> 5;
    const int wm = (wid & 1) * 64, wn = (wid >> 1) * (NTILE / 4);
    const uint32_t sb = s2u(smc);

    float acc[4][NTT][4];
    #pragma unroll
    for (int i = 0; i < 4; i++)
        #pragma unroll
        for (int j = 0; j < NTT; j++)
            #pragma unroll
            for (int k = 0; k < 4; k++) acc[i][j][k] = 0.0f;

    auto load_chunk = [&](int kc, int s) {
        uint32_t st = sb + s * STG;
        #pragma unroll
        for (int i = 0; i < 2; i++) {
            int idx = tid + 256 * i;
            int r = idx >> 2, cq = idx & 3;
            uint32_t off = r * 64 + ((cq * 16) ^ ((r & 3) << 4));
            size_t src = (size_t)(m0 + r) * K + kc * 32 + cq * 8;
            cpa16(st + off, Ah + src);
            cpa16(st + ASZ + off, Al + src);
        }
        constexpr int BCH = BSZ / 16;
        constexpr int CPR = NTILE / 8;
        #pragma unroll
        for (int i = 0; i < (BCH + 255) / 256; i++) {
            int idx = tid + 256 * i;
            if (BCH < 256 || idx < BCH) {
                int r = idx / CPR, cq = idx % CPR;
                uint32_t off = 2 * ASZ + r * RB + ((cq * 16) ^ ((r & 7) << 4));
                size_t src = (size_t)(kc * 32 + r) * N + n0 + cq * 8;
                cpa16(st + off, Bh + src);
                cpa16(st + BSZ + off, Bl + src);
            }
        }
    };

    load_chunk(0, 0);
    CP_COMMIT();

    const int NC = K / 32;
    for (int kc = 0; kc < NC; kc++) {
        if (kc + 1 < NC) {
            load_chunk(kc + 1, (kc + 1) & 1);
            CP_COMMIT();
            CP_WAIT(1);
        } else {
            CP_WAIT(0);
        }
        __syncthreads();

        uint32_t st = sb + (kc & 1) * STG;
        #pragma unroll
        for (int ks = 0; ks < 2; ks++) {
            uint32_t af[2][4][4], bfr[2][NTT][2];
            #pragma unroll
            for (int mt = 0; mt < 4; mt++) {
                int row = wm + mt * 16 + (l & 15);
                uint32_t off = row * 64 + (((uint32_t)(ks * 32 + (l >> 4) * 16)) ^ ((row & 3) << 4));
                ldm4(af[0][mt], st + off);
                ldm4(af[1][mt], st + ASZ + off);
            }
            #pragma unroll
            for (int bg = 0; bg < NTT / 2; bg++) {
                int k = ks * 16 + (l & 7) + (((l >> 3) & 1) << 3);
                uint32_t byt = (uint32_t)((wn + bg * 16) * 2 + ((l >> 4) << 4));
                uint32_t off = 2 * ASZ + k * RB + (byt ^ ((k & 7) << 4));
                uint32_t t0[4], t1[4];
                ldm4t(t0, st + off);
                ldm4t(t1, st + BSZ + off);
                bfr[0][2*bg][0] = t0[0]; bfr[0][2*bg][1] = t0[1];
                bfr[0][2*bg+1][0] = t0[2]; bfr[0][2*bg+1][1] = t0[3];
                bfr[1][2*bg][0] = t1[0]; bfr[1][2*bg][1] = t1[1];
                bfr[1][2*bg+1][0] = t1[2]; bfr[1][2*bg+1][1] = t1[3];
            }
            #pragma unroll
            for (int mt = 0; mt < 4; mt++)
                #pragma unroll
                for (int nt = 0; nt < NTT; nt++) {
                    mmabf(acc[mt][nt], af[0][mt], bfr[0][nt]);
                    mmabf(acc[mt][nt], af[0][mt], bfr[1][nt]);
                    mmabf(acc[mt][nt], af[1][mt], bfr[0][nt]);
                }
        }
        __syncthreads();
    }

    #pragma unroll
    for (int mt = 0; mt < 4; mt++)
        #pragma unroll
        for (int nt = 0; nt < NTT; nt++) {
            int rg = m0 + wm + mt * 16 + (l >> 2);
            int cg = n0 + wn + nt * 8 + (l & 3) * 2;
            if (EPI == 0) {
                *(float2*)(Cf + (size_t)rg * N + cg)       = make_float2(acc[mt][nt][0], acc[mt][nt][1]);
                *(float2*)(Cf + (size_t)(rg + 8) * N + cg) = make_float2(acc[mt][nt][2], acc[mt][nt][3]);
            } else {
                uint32_t h0, l0, h1, l1;
                split2pk(acc[mt][nt][0] * scale, acc[mt][nt][1] * scale, h0, l0);
                split2pk(acc[mt][nt][2] * scale, acc[mt][nt][3] * scale, h1, l1);
                ((uint32_t*)Ch)[((size_t)rg * N + cg) >> 1] = h0;
                ((uint32_t*)Cl)[((size_t)rg * N + cg) >> 1] = l0;
                ((uint32_t*)Ch)[((size_t)(rg + 8) * N + cg) >> 1] = h1;
                ((uint32_t*)Cl)[((size_t)(rg + 8) * N + cg) >> 1] = l1;
            }
        }
}

// Merged Q/K/V projection: grid (10, 32).
__global__ __launch_bounds__(256, 2)
void qkv_proj(const bf16* __restrict__ Xh, const bf16* __restrict__ Xl,
              const bf16* __restrict__ Wqh, const bf16* __restrict__ Wql,
              const bf16* __restrict__ Wkh, const bf16* __restrict__ Wkl,
              const bf16* __restrict__ Wvh, const bf16* __restrict__ Wvl,
              bf16* Qh, bf16* Ql, bf16* Kh, bf16* Kl, bf16* Vh, bf16* Vl)
{
    extern __shared__ char smc[];
    const int bx = blockIdx.x, m0 = blockIdx.y * 128;
    if (bx < 8) {
        gemm_body<128, 1>(Xh, Xl, Wqh, Wql, nullptr, Qh, Ql,
                          HIDDIM, HIDDIM, QK_SCALE_LOG2E, m0, bx * 128, smc);
    } else if (bx == 8) {
        gemm_body<64, 1>(Xh, Xl, Wkh, Wkl, nullptr, Kh, Kl,
                         HD, HIDDIM, 1.0f, m0, 0, smc);
    } else {
        gemm_body<64, 1>(Xh, Xl, Wvh, Wvl, nullptr, Vh, Vl,
                         HD, HIDDIM, 1.0f, m0, 0, smc);
    }
}

__global__ __launch_bounds__(256, 2)
void o_proj(const bf16* __restrict__ Ahp, const bf16* __restrict__ Alp,
            const bf16* __restrict__ Woh, const bf16* __restrict__ Wol,
            float* __restrict__ out)
{
    extern __shared__ char smc[];
    gemm_body<128, 0>(Ahp, Alp, Woh, Wol, out, nullptr, nullptr,
                      HIDDIM, HIDDIM, 1.0f, blockIdx.y * 128, blockIdx.x * 128, smc);
}

// ---------------------------------------------------------------------------
// Flash attention. R8: QK with 3 independent accumulators per S fragment.
// ---------------------------------------------------------------------------
#define FQH  0
#define FQL  32768
#define FKV  65536
#define FSMEM 196608
#define QT   256

__global__ __launch_bounds__(512, 1)
void flash_bf(const bf16* __restrict__ Qh, const bf16* __restrict__ Ql,
              const bf16* __restrict__ Kh, const bf16* __restrict__ Kl,
              const bf16* __restrict__ Vh, const bf16* __restrict__ Vl,
              bf16* __restrict__ Ahg, bf16* __restrict__ Alg)
{
    extern __shared__ char smc[];
    const uint32_t sb = s2u(smc);

    const int tid = threadIdx.x, l = tid & 31, wid = tid >> 5;
    const int q0 = blockIdx.x * QT, h = blockIdx.y, b = blockIdx.z;

    #pragma unroll
    for (int i = 0; i < 4; i++) {
        int idx = tid + 512 * i;
        int r = idx >> 3, cq = idx & 7;
        uint32_t off = r * 128 + ((cq * 16) ^ ((r & 7) << 4));
        size_t src = (size_t)(b * SEQ + q0 + r) * HIDDIM + h * HD + cq * 8;
        cpa16(sb + FQH + off, Qh + src);
        cpa16(sb + FQL + off, Ql + src);
    }
    #pragma unroll
    for (int i = 0; i < 2; i++) {
        int idx = tid + 512 * i;
        int r = idx >> 3, cq = idx & 7;
        uint32_t off = r * 128 + ((cq * 16) ^ ((r & 7) << 4));
        size_t src = (size_t)(b * SEQ + r) * HD + cq * 8;
        cpa16(sb + FKV + off,         Kh + src);
        cpa16(sb + FKV + 16384 + off, Kl + src);
        cpa16(sb + FKV + 32768 + off, Vh + src);
        cpa16(sb + FKV + 49152 + off, Vl + src);
    }
    CP_COMMIT();

    uint32_t qf[2][4][4];
    float o[8][4];
    #pragma unroll
    for (int i = 0; i < 8; i++)
        #pragma unroll
        for (int k = 0; k < 4; k++) o[i][k] = 0.0f;
    float preg[2] = {0.0f, 0.0f};

    for (int t = 0; t < 16; t++) {
        if (t < 15) {
            uint32_t st = sb + FKV + ((t + 1) & 1) * 65536;
            #pragma unroll
            for (int i = 0; i < 2; i++) {
                int idx = tid + 512 * i;
                int r = idx >> 3, cq = idx & 7;
                uint32_t off = r * 128 + ((cq * 16) ^ ((r & 7) << 4));
                size_t src = (size_t)(b * SEQ + (t + 1) * 128 + r) * HD + cq * 8;
                cpa16(st + off,         Kh + src);
                cpa16(st + 16384 + off, Kl + src);
                cpa16(st + 32768 + off, Vh + src);
                cpa16(st + 49152 + off, Vl + src);
            }
            CP_COMMIT();
            CP_WAIT(1);
        } else {
            CP_WAIT(0);
        }
        __syncthreads();

        if (t == 0) {
            #pragma unroll
            for (int ks = 0; ks < 4; ks++) {
                int row = wid * 16 + (l & 15);
                uint32_t off = row * 128 + (((uint32_t)(ks * 32 + (l >> 4) * 16)) ^ ((row & 7) << 4));
                ldm4(qf[0][ks], sb + FQH + off);
                ldm4(qf[1][ks], sb + FQL + off);
            }
        }

        const uint32_t stK = sb + FKV + (t & 1) * 65536;
        const uint32_t stV = stK + 32768;

        #pragma unroll
        for (int g = 0; g < 8; g++) {
            // --- QK: 3 independent accumulators per fragment (6 chains) ---
            float sA[2][4], sB[2][4], sC[2][4];
            #pragma unroll
            for (int i = 0; i < 2; i++)
                #pragma unroll
                for (int k = 0; k < 4; k++) { sA[i][k] = 0.0f; sB[i][k] = 0.0f; sC[i][k] = 0.0f; }

            int krow = g * 16 + (l & 7) + ((l >> 4) << 3);
            #pragma unroll
            for (int ks = 0; ks < 4; ks++) {
                uint32_t off = krow * 128 + (((uint32_t)(ks * 32 + ((l >> 3) & 1) * 16)) ^ ((krow & 7) << 4));
                uint32_t t0[4], t1[4];
                ldm4(t0, stK + off);
                ldm4(t1, stK + 16384 + off);
                uint32_t bh0[2] = {t0[0], t0[1]}, bh1[2] = {t0[2], t0[3]};
                uint32_t bl0[2] = {t1[0], t1[1]}, bl1[2] = {t1[2], t1[3]};
                mmabf(sA[0], qf[0][ks], bh0);
                mmabf(sB[0], qf[0][ks], bl0);
                mmabf(sC[0], qf[1][ks], bh0);
                mmabf(sA[1], qf[0][ks], bh1);
                mmabf(sB[1], qf[0][ks], bl1);
                mmabf(sC[1], qf[1][ks], bh1);
            }

            // merge + exp2 + row-sum
            float s2[2][4];
            #pragma unroll
            for (int i = 0; i < 2; i++) {
                #pragma unroll
                for (int k = 0; k < 4; k++)
                    s2[i][k] = exp2f((sA[i][k] + sB[i][k]) + sC[i][k]);
                preg[0] += s2[i][0] + s2[i][1];
                preg[1] += s2[i][2] + s2[i][3];
            }

            uint32_t aH[4], aL[4];
            split2pk(s2[0][0], s2[0][1], aH[0], aL[0]);
            split2pk(s2[0][2], s2[0][3], aH[1], aL[1]);
            split2pk(s2[1][0], s2[1][1], aH[2], aL[2]);
            split2pk(s2[1][2], s2[1][3], aH[3], aL[3]);

            int key = g * 16 + (l & 7) + (((l >> 3) & 1) << 3);
            #pragma unroll
            for (int bg = 0; bg < 4; bg++) {
                uint32_t byt = (uint32_t)(bg * 32 + ((l >> 4) << 4));
                uint32_t off = key * 128 + (byt ^ ((key & 7) << 4));
                uint32_t t0[4], t1[4];
                ldm4t(t0, stV + off);
                ldm4t(t1, stV + 16384 + off);
                uint32_t bh0[2] = {t0[0], t0[1]}, bh1[2] = {t0[2], t0[3]};
                uint32_t bl0[2] = {t1[0], t1[1]}, bl1[2] = {t1[2], t1[3]};
                mmabf(o[2*bg],   aH, bh0);
                mmabf(o[2*bg],   aH, bl0);
                mmabf(o[2*bg],   aL, bh0);
                mmabf(o[2*bg+1], aH, bh1);
                mmabf(o[2*bg+1], aH, bl1);
                mmabf(o[2*bg+1], aL, bh1);
            }
        }
        __syncthreads();
    }

    #pragma unroll
    for (int i = 0; i < 2; i++) {
        preg[i] += __shfl_xor_sync(0xffffffffu, preg[i], 1);
        preg[i] += __shfl_xor_sync(0xffffffffu, preg[i], 2);
    }
    float inv0 = 1.0f / preg[0], inv1 = 1.0f / preg[1];

    int r0 = wid * 16 + (l >> 2);
    size_t base0 = (size_t)(b * SEQ + q0 + r0) * HIDDIM + h * HD;
    size_t base1 = (size_t)(b * SEQ + q0 + r0 + 8) * HIDDIM + h * HD;
    #pragma unroll
    for (int nt = 0; nt < 8; nt++) {
        int col = nt * 8 + (l & 3) * 2;
        uint32_t hi, lo;
        split2pk(o[nt][0] * inv0, o[nt][1] * inv0, hi, lo);
        ((uint32_t*)Ahg)[(base0 + col) >> 1] = hi;
        ((uint32_t*)Alg)[(base0 + col) >> 1] = lo;
        split2pk(o[nt][2] * inv1, o[nt][3] * inv1, hi, lo);
        ((uint32_t*)Ahg)[(base1 + col) >> 1] = hi;
        ((uint32_t*)Alg)[(base1 + col) >> 1] = lo;
    }
}

// ---------------------------------------------------------------------------
extern "C" void kernel_launch(void* const* d_in, const int* in_sizes, int n_in,
                              void* d_out, int out_size)
{
    const float* hs = (const float*)d_in[0];
    const float* Wq = (const float*)d_in[1];
    const float* Wk = (const float*)d_in[2];
    const float* Wv = (const float*)d_in[3];
    const float* Wo = (const float*)d_in[4];
    float* out = (float*)d_out;

    bf16 *Xh, *Xl, *Wqh, *Wql, *Wkh, *Wkl, *Wvh, *Wvl, *Woh, *Wol;
    bf16 *Qh, *Ql, *Kh, *Kl, *Vh, *Vl, *Ahp, *Alp;
    cudaGetSymbolAddress((void**)&Xh, g_Xh);   cudaGetSymbolAddress((void**)&Xl, g_Xl);
    cudaGetSymbolAddress((void**)&Wqh, g_Wqh); cudaGetSymbolAddress((void**)&Wql, g_Wql);
    cudaGetSymbolAddress((void**)&Wkh, g_Wkh); cudaGetSymbolAddress((void**)&Wkl, g_Wkl);
    cudaGetSymbolAddress((void**)&Wvh, g_Wvh); cudaGetSymbolAddress((void**)&Wvl, g_Wvl);
    cudaGetSymbolAddress((void**)&Woh, g_Woh); cudaGetSymbolAddress((void**)&Wol, g_Wol);
    cudaGetSymbolAddress((void**)&Qh, g_Qh);   cudaGetSymbolAddress((void**)&Ql, g_Ql);
    cudaGetSymbolAddress((void**)&Kh, g_Kh);   cudaGetSymbolAddress((void**)&Kl, g_Kl);
    cudaGetSymbolAddress((void**)&Vh, g_Vh);   cudaGetSymbolAddress((void**)&Vl, g_Vl);
    cudaGetSymbolAddress((void**)&Ahp, g_Ah);  cudaGetSymbolAddress((void**)&Alp, g_Al);

    constexpr int STG128 = 2 * (128 * 64) + 2 * (32 * 128 * 2);  // 32768
    cudaFuncSetAttribute(qkv_proj, cudaFuncAttributeMaxDynamicSharedMemorySize, 2 * STG128);
    cudaFuncSetAttribute(o_proj,   cudaFuncAttributeMaxDynamicSharedMemorySize, 2 * STG128);
    cudaFuncSetAttribute(flash_bf, cudaFuncAttributeMaxDynamicSharedMemorySize, FSMEM);

    split_all<<<R_WO / 256, 256>>>(hs, Wq, Wk, Wv, Wo,
                                   Xh, Xl, Wqh, Wql, Wkh, Wkl, Wvh, Wvl, Woh, Wol);
    qkv_proj<<<dim3(10, MTOT / 128), 256, 2 * STG128>>>(
        Xh, Xl, Wqh, Wql, Wkh, Wkl, Wvh, Wvl, Qh, Ql, Kh, Kl, Vh, Vl);
    flash_bf<<<dim3(SEQ / QT, NHEAD, NB), 512, FSMEM>>>(Qh, Ql, Kh, Kl, Vh, Vl, Ahp, Alp);
    o_proj<<<dim3(HIDDIM / 128, MTOT / 128), 256, 2 * STG128>>>(Ahp, Alp, Woh, Wol, out);
}

// round 9
// speedup vs baseline: 1.5856x; 1.5856x over previous
#include <cuda_runtime.h>
#include <cuda_bf16.h>
#include <cstdint>

// ---------------------------------------------------------------------------
// MQA, split-bf16 mma.sync. R9: R7 structure; flash QK uses TWO accumulator
// sets (hi*hi+lo*hi -> sA, hi*lo -> sB): chain 12 -> 8, +8 regs (no spill).
// o_proj unchanged = clock control vs R8 anomaly.
// ---------------------------------------------------------------------------
#define NB     2
#define SEQ    2048
#define HIDDIM 1024
#define NHEAD  16
#define HD     64
#define MTOT   (NB * SEQ)
#define QK_SCALE_LOG2E 0.180336880111120f   // 0.125 * log2(e)

typedef __nv_bfloat16 bf16;

__device__ bf16 g_Xh[MTOT * HIDDIM], g_Xl[MTOT * HIDDIM];
__device__ bf16 g_Wqh[HIDDIM * HIDDIM], g_Wql[HIDDIM * HIDDIM];
__device__ bf16 g_Wkh[HIDDIM * HD],     g_Wkl[HIDDIM * HD];
__device__ bf16 g_Wvh[HIDDIM * HD],     g_Wvl[HIDDIM * HD];
__device__ bf16 g_Woh[HIDDIM * HIDDIM], g_Wol[HIDDIM * HIDDIM];
__device__ bf16 g_Qh[MTOT * HIDDIM], g_Ql[MTOT * HIDDIM];
__device__ bf16 g_Kh[MTOT * HD],     g_Kl[MTOT * HD];
__device__ bf16 g_Vh[MTOT * HD],     g_Vl[MTOT * HD];
__device__ bf16 g_Ah[MTOT * HIDDIM], g_Al[MTOT * HIDDIM];

// ---------------- helpers ----------------
__device__ __forceinline__ uint32_t s2u(const void* p) {
    uint32_t a;
    asm("{ .reg .u64 t; cvta.to.shared.u64 t, %1; cvt.u32.u64 %0, t; }"
        : "=r"(a) : "l"(p));
    return a;
}
__device__ __forceinline__ void cpa16(uint32_t dst, const void* src) {
    asm volatile("cp.async.cg.shared.global [%0], [%1], 16;" :: "r"(dst), "l"(src));
}
#define CP_COMMIT() asm volatile("cp.async.commit_group;" ::: "memory")
#define CP_WAIT(n)  asm volatile("cp.async.wait_group %0;" :: "n"(n) : "memory")

__device__ __forceinline__ void ldm4(uint32_t* r, uint32_t a) {
    asm volatile("ldmatrix.sync.aligned.m8n8.x4.shared.b16 {%0,%1,%2,%3}, [%4];"
        : "=r"(r[0]), "=r"(r[1]), "=r"(r[2]), "=r"(r[3]) : "r"(a));
}
__device__ __forceinline__ void ldm4t(uint32_t* r, uint32_t a) {
    asm volatile("ldmatrix.sync.aligned.m8n8.x4.trans.shared.b16 {%0,%1,%2,%3}, [%4];"
        : "=r"(r[0]), "=r"(r[1]), "=r"(r[2]), "=r"(r[3]) : "r"(a));
}
__device__ __forceinline__ void mmabf(float* d, const uint32_t* a, const uint32_t* b) {
    asm volatile("mma.sync.aligned.m16n8k16.row.col.f32.bf16.bf16.f32 "
        "{%0,%1,%2,%3},{%4,%5,%6,%7},{%8,%9},{%0,%1,%2,%3};"
        : "+f"(d[0]), "+f"(d[1]), "+f"(d[2]), "+f"(d[3])
        : "r"(a[0]), "r"(a[1]), "r"(a[2]), "r"(a[3]), "r"(b[0]), "r"(b[1]));
}
__device__ __forceinline__ void split2pk(float a, float b, uint32_t& hi, uint32_t& lo) {
    __nv_bfloat16 ha = __float2bfloat16_rn(a), hb = __float2bfloat16_rn(b);
    float ra = a - __bfloat162float(ha), rb = b - __bfloat162float(hb);
    __nv_bfloat16 la = __float2bfloat16_rn(ra), lb = __float2bfloat16_rn(rb);
    hi = (uint32_t)__bfloat16_as_ushort(ha) | ((uint32_t)__bfloat16_as_ushort(hb) << 16);
    lo = (uint32_t)__bfloat16_as_ushort(la) | ((uint32_t)__bfloat16_as_ushort(lb) << 16);
}

// ---------------------------------------------------------------------------
// Fused split: all 5 inputs, one launch.
// ---------------------------------------------------------------------------
#define R_X  1048576
#define R_WQ (R_X + 262144)
#define R_WK (R_WQ + 16384)
#define R_WV (R_WK + 16384)
#define R_WO (R_WV + 262144)

__global__ void split_all(const float* __restrict__ x,  const float* __restrict__ wq,
                          const float* __restrict__ wk, const float* __restrict__ wv,
                          const float* __restrict__ wo,
                          bf16* xh, bf16* xl, bf16* qh, bf16* ql, bf16* kh, bf16* kl,
                          bf16* vh, bf16* vl, bf16* oh, bf16* ol)
{
    int i = blockIdx.x * blockDim.x + threadIdx.x;
    const float* in; bf16 *hi, *lo; int j;
    if (i < R_X)       { in = x;  hi = xh; lo = xl; j = i; }
    else if (i < R_WQ) { in = wq; hi = qh; lo = ql; j = i - R_X; }
    else if (i < R_WK) { in = wk; hi = kh; lo = kl; j = i - R_WQ; }
    else if (i < R_WV) { in = wv; hi = vh; lo = vl; j = i - R_WK; }
    else               { in = wo; hi = oh; lo = ol; j = i - R_WV; }
    float4 v = ((const float4*)in)[j];
    uint32_t h0, l0, h1, l1;
    split2pk(v.x, v.y, h0, l0);
    split2pk(v.z, v.w, h1, l1);
    ((uint2*)hi)[j] = make_uint2(h0, h1);
    ((uint2*)lo)[j] = make_uint2(l0, l1);
}

// ---------------------------------------------------------------------------
// GEMM body: C[128 x NTILE] tile of A[M,K]*B[K,N]; cp.async 2-stage.
// ---------------------------------------------------------------------------
template<int NTILE, int EPI>
__device__ __forceinline__
void gemm_body(const bf16* __restrict__ Ah, const bf16* __restrict__ Al,
               const bf16* __restrict__ Bh, const bf16* __restrict__ Bl,
               float* __restrict__ Cf, bf16* __restrict__ Ch, bf16* __restrict__ Cl,
               int N, int K, float scale, int m0, int n0, char* smc)
{
    constexpr int ASZ = 128 * 64;
    constexpr int BSZ = 32 * NTILE * 2;
    constexpr int STG = 2 * ASZ + 2 * BSZ;
    constexpr int RB  = NTILE * 2;
    constexpr int NTT = NTILE / 32;

    const int tid = threadIdx.x, l = tid & 31, wid = tid >> 5;
    const int wm = (wid & 1) * 64, wn = (wid >> 1) * (NTILE / 4);
    const uint32_t sb = s2u(smc);

    float acc[4][NTT][4];
    #pragma unroll
    for (int i = 0; i < 4; i++)
        #pragma unroll
        for (int j = 0; j < NTT; j++)
            #pragma unroll
            for (int k = 0; k < 4; k++) acc[i][j][k] = 0.0f;

    auto load_chunk = [&](int kc, int s) {
        uint32_t st = sb + s * STG;
        #pragma unroll
        for (int i = 0; i < 2; i++) {
            int idx = tid + 256 * i;
            int r = idx >> 2, cq = idx & 3;
            uint32_t off = r * 64 + ((cq * 16) ^ ((r & 3) << 4));
            size_t src = (size_t)(m0 + r) * K + kc * 32 + cq * 8;
            cpa16(st + off, Ah + src);
            cpa16(st + ASZ + off, Al + src);
        }
        constexpr int BCH = BSZ / 16;
        constexpr int CPR = NTILE / 8;
        #pragma unroll
        for (int i = 0; i < (BCH + 255) / 256; i++) {
            int idx = tid + 256 * i;
            if (BCH < 256 || idx < BCH) {
                int r = idx / CPR, cq = idx % CPR;
                uint32_t off = 2 * ASZ + r * RB + ((cq * 16) ^ ((r & 7) << 4));
                size_t src = (size_t)(kc * 32 + r) * N + n0 + cq * 8;
                cpa16(st + off, Bh + src);
                cpa16(st + BSZ + off, Bl + src);
            }
        }
    };

    load_chunk(0, 0);
    CP_COMMIT();

    const int NC = K / 32;
    for (int kc = 0; kc < NC; kc++) {
        if (kc + 1 < NC) {
            load_chunk(kc + 1, (kc + 1) & 1);
            CP_COMMIT();
            CP_WAIT(1);
        } else {
            CP_WAIT(0);
        }
        __syncthreads();

        uint32_t st = sb + (kc & 1) * STG;
        #pragma unroll
        for (int ks = 0; ks < 2; ks++) {
            uint32_t af[2][4][4], bfr[2][NTT][2];
            #pragma unroll
            for (int mt = 0; mt < 4; mt++) {
                int row = wm + mt * 16 + (l & 15);
                uint32_t off = row * 64 + (((uint32_t)(ks * 32 + (l >> 4) * 16)) ^ ((row & 3) << 4));
                ldm4(af[0][mt], st + off);
                ldm4(af[1][mt], st + ASZ + off);
            }
            #pragma unroll
            for (int bg = 0; bg < NTT / 2; bg++) {
                int k = ks * 16 + (l & 7) + (((l >> 3) & 1) << 3);
                uint32_t byt = (uint32_t)((wn + bg * 16) * 2 + ((l >> 4) << 4));
                uint32_t off = 2 * ASZ + k * RB + (byt ^ ((k & 7) << 4));
                uint32_t t0[4], t1[4];
                ldm4t(t0, st + off);
                ldm4t(t1, st + BSZ + off);
                bfr[0][2*bg][0] = t0[0]; bfr[0][2*bg][1] = t0[1];
                bfr[0][2*bg+1][0] = t0[2]; bfr[0][2*bg+1][1] = t0[3];
                bfr[1][2*bg][0] = t1[0]; bfr[1][2*bg][1] = t1[1];
                bfr[1][2*bg+1][0] = t1[2]; bfr[1][2*bg+1][1] = t1[3];
            }
            #pragma unroll
            for (int mt = 0; mt < 4; mt++)
                #pragma unroll
                for (int nt = 0; nt < NTT; nt++) {
                    mmabf(acc[mt][nt], af[0][mt], bfr[0][nt]);
                    mmabf(acc[mt][nt], af[0][mt], bfr[1][nt]);
                    mmabf(acc[mt][nt], af[1][mt], bfr[0][nt]);
                }
        }
        __syncthreads();
    }

    #pragma unroll
    for (int mt = 0; mt < 4; mt++)
        #pragma unroll
        for (int nt = 0; nt < NTT; nt++) {
            int rg = m0 + wm + mt * 16 + (l >> 2);
            int cg = n0 + wn + nt * 8 + (l & 3) * 2;
            if (EPI == 0) {
                *(float2*)(Cf + (size_t)rg * N + cg)       = make_float2(acc[mt][nt][0], acc[mt][nt][1]);
                *(float2*)(Cf + (size_t)(rg + 8) * N + cg) = make_float2(acc[mt][nt][2], acc[mt][nt][3]);
            } else {
                uint32_t h0, l0, h1, l1;
                split2pk(acc[mt][nt][0] * scale, acc[mt][nt][1] * scale, h0, l0);
                split2pk(acc[mt][nt][2] * scale, acc[mt][nt][3] * scale, h1, l1);
                ((uint32_t*)Ch)[((size_t)rg * N + cg) >> 1] = h0;
                ((uint32_t*)Cl)[((size_t)rg * N + cg) >> 1] = l0;
                ((uint32_t*)Ch)[((size_t)(rg + 8) * N + cg) >> 1] = h1;
                ((uint32_t*)Cl)[((size_t)(rg + 8) * N + cg) >> 1] = l1;
            }
        }
}

// Merged Q/K/V projection: grid (10, 32).
__global__ __launch_bounds__(256, 2)
void qkv_proj(const bf16* __restrict__ Xh, const bf16* __restrict__ Xl,
              const bf16* __restrict__ Wqh, const bf16* __restrict__ Wql,
              const bf16* __restrict__ Wkh, const bf16* __restrict__ Wkl,
              const bf16* __restrict__ Wvh, const bf16* __restrict__ Wvl,
              bf16* Qh, bf16* Ql, bf16* Kh, bf16* Kl, bf16* Vh, bf16* Vl)
{
    extern __shared__ char smc[];
    const int bx = blockIdx.x, m0 = blockIdx.y * 128;
    if (bx < 8) {
        gemm_body<128, 1>(Xh, Xl, Wqh, Wql, nullptr, Qh, Ql,
                          HIDDIM, HIDDIM, QK_SCALE_LOG2E, m0, bx * 128, smc);
    } else if (bx == 8) {
        gemm_body<64, 1>(Xh, Xl, Wkh, Wkl, nullptr, Kh, Kl,
                         HD, HIDDIM, 1.0f, m0, 0, smc);
    } else {
        gemm_body<64, 1>(Xh, Xl, Wvh, Wvl, nullptr, Vh, Vl,
                         HD, HIDDIM, 1.0f, m0, 0, smc);
    }
}

__global__ __launch_bounds__(256, 2)
void o_proj(const bf16* __restrict__ Ahp, const bf16* __restrict__ Alp,
            const bf16* __restrict__ Woh, const bf16* __restrict__ Wol,
            float* __restrict__ out)
{
    extern __shared__ char smc[];
    gemm_body<128, 0>(Ahp, Alp, Woh, Wol, out, nullptr, nullptr,
                      HIDDIM, HIDDIM, 1.0f, blockIdx.y * 128, blockIdx.x * 128, smc);
}

// ---------------------------------------------------------------------------
// Flash attention: streaming softmax; QK with 2 accumulator sets (4 chains).
// ---------------------------------------------------------------------------
#define FQH  0
#define FQL  32768
#define FKV  65536
#define FSMEM 196608
#define QT   256

__global__ __launch_bounds__(512, 1)
void flash_bf(const bf16* __restrict__ Qh, const bf16* __restrict__ Ql,
              const bf16* __restrict__ Kh, const bf16* __restrict__ Kl,
              const bf16* __restrict__ Vh, const bf16* __restrict__ Vl,
              bf16* __restrict__ Ahg, bf16* __restrict__ Alg)
{
    extern __shared__ char smc[];
    const uint32_t sb = s2u(smc);

    const int tid = threadIdx.x, l = tid & 31, wid = tid >> 5;
    const int q0 = blockIdx.x * QT, h = blockIdx.y, b = blockIdx.z;

    #pragma unroll
    for (int i = 0; i < 4; i++) {
        int idx = tid + 512 * i;
        int r = idx >> 3, cq = idx & 7;
        uint32_t off = r * 128 + ((cq * 16) ^ ((r & 7) << 4));
        size_t src = (size_t)(b * SEQ + q0 + r) * HIDDIM + h * HD + cq * 8;
        cpa16(sb + FQH + off, Qh + src);
        cpa16(sb + FQL + off, Ql + src);
    }
    #pragma unroll
    for (int i = 0; i < 2; i++) {
        int idx = tid + 512 * i;
        int r = idx >> 3, cq = idx & 7;
        uint32_t off = r * 128 + ((cq * 16) ^ ((r & 7) << 4));
        size_t src = (size_t)(b * SEQ + r) * HD + cq * 8;
        cpa16(sb + FKV + off,         Kh + src);
        cpa16(sb + FKV + 16384 + off, Kl + src);
        cpa16(sb + FKV + 32768 + off, Vh + src);
        cpa16(sb + FKV + 49152 + off, Vl + src);
    }
    CP_COMMIT();

    uint32_t qf[2][4][4];
    float o[8][4];
    #pragma unroll
    for (int i = 0; i < 8; i++)
        #pragma unroll
        for (int k = 0; k < 4; k++) o[i][k] = 0.0f;
    float preg[2] = {0.0f, 0.0f};

    for (int t = 0; t < 16; t++) {
        if (t < 15) {
            uint32_t st = sb + FKV + ((t + 1) & 1) * 65536;
            #pragma unroll
            for (int i = 0; i < 2; i++) {
                int idx = tid + 512 * i;
                int r = idx >> 3, cq = idx & 7;
                uint32_t off = r * 128 + ((cq * 16) ^ ((r & 7) << 4));
                size_t src = (size_t)(b * SEQ + (t + 1) * 128 + r) * HD + cq * 8;
                cpa16(st + off,         Kh + src);
                cpa16(st + 16384 + off, Kl + src);
                cpa16(st + 32768 + off, Vh + src);
                cpa16(st + 49152 + off, Vl + src);
            }
            CP_COMMIT();
            CP_WAIT(1);
        } else {
            CP_WAIT(0);
        }
        __syncthreads();

        if (t == 0) {
            #pragma unroll
            for (int ks = 0; ks < 4; ks++) {
                int row = wid * 16 + (l & 15);
                uint32_t off = row * 128 + (((uint32_t)(ks * 32 + (l >> 4) * 16)) ^ ((row & 7) << 4));
                ldm4(qf[0][ks], sb + FQH + off);
                ldm4(qf[1][ks], sb + FQL + off);
            }
        }

        const uint32_t stK = sb + FKV + (t & 1) * 65536;
        const uint32_t stV = stK + 32768;

        #pragma unroll
        for (int g = 0; g < 8; g++) {
            // --- QK: 2 accumulator sets per fragment (4 chains) ---
            float sA[2][4], sB[2][4];
            #pragma unroll
            for (int i = 0; i < 2; i++)
                #pragma unroll
                for (int k = 0; k < 4; k++) { sA[i][k] = 0.0f; sB[i][k] = 0.0f; }

            int krow = g * 16 + (l & 7) + ((l >> 4) << 3);
            #pragma unroll
            for (int ks = 0; ks < 4; ks++) {
                uint32_t off = krow * 128 + (((uint32_t)(ks * 32 + ((l >> 3) & 1) * 16)) ^ ((krow & 7) << 4));
                uint32_t t0[4], t1[4];
                ldm4(t0, stK + off);
                ldm4(t1, stK + 16384 + off);
                uint32_t bh0[2] = {t0[0], t0[1]}, bh1[2] = {t0[2], t0[3]};
                uint32_t bl0[2] = {t1[0], t1[1]}, bl1[2] = {t1[2], t1[3]};
                mmabf(sA[0], qf[0][ks], bh0);   // hi*hi -> A
                mmabf(sB[0], qf[0][ks], bl0);   // hi*lo -> B
                mmabf(sA[1], qf[0][ks], bh1);
                mmabf(sB[1], qf[0][ks], bl1);
                mmabf(sA[0], qf[1][ks], bh0);   // lo*hi -> A
                mmabf(sA[1], qf[1][ks], bh1);
            }

            float s2[2][4];
            #pragma unroll
            for (int i = 0; i < 2; i++) {
                #pragma unroll
                for (int k = 0; k < 4; k++)
                    s2[i][k] = exp2f(sA[i][k] + sB[i][k]);
                preg[0] += s2[i][0] + s2[i][1];
                preg[1] += s2[i][2] + s2[i][3];
            }

            uint32_t aH[4], aL[4];
            split2pk(s2[0][0], s2[0][1], aH[0], aL[0]);
            split2pk(s2[0][2], s2[0][3], aH[1], aL[1]);
            split2pk(s2[1][0], s2[1][1], aH[2], aL[2]);
            split2pk(s2[1][2], s2[1][3], aH[3], aL[3]);

            int key = g * 16 + (l & 7) + (((l >> 3) & 1) << 3);
            #pragma unroll
            for (int bg = 0; bg < 4; bg++) {
                uint32_t byt = (uint32_t)(bg * 32 + ((l >> 4) << 4));
                uint32_t off = key * 128 + (byt ^ ((key & 7) << 4));
                uint32_t t0[4], t1[4];
                ldm4t(t0, stV + off);
                ldm4t(t1, stV + 16384 + off);
                uint32_t bh0[2] = {t0[0], t0[1]}, bh1[2] = {t0[2], t0[3]};
                uint32_t bl0[2] = {t1[0], t1[1]}, bl1[2] = {t1[2], t1[3]};
                mmabf(o[2*bg],   aH, bh0);
                mmabf(o[2*bg],   aH, bl0);
                mmabf(o[2*bg],   aL, bh0);
                mmabf(o[2*bg+1], aH, bh1);
                mmabf(o[2*bg+1], aH, bl1);
                mmabf(o[2*bg+1], aL, bh1);
            }
        }
        __syncthreads();
    }

    #pragma unroll
    for (int i = 0; i < 2; i++) {
        preg[i] += __shfl_xor_sync(0xffffffffu, preg[i], 1);
        preg[i] += __shfl_xor_sync(0xffffffffu, preg[i], 2);
    }
    float inv0 = 1.0f / preg[0], inv1 = 1.0f / preg[1];

    int r0 = wid * 16 + (l >> 2);
    size_t base0 = (size_t)(b * SEQ + q0 + r0) * HIDDIM + h * HD;
    size_t base1 = (size_t)(b * SEQ + q0 + r0 + 8) * HIDDIM + h * HD;
    #pragma unroll
    for (int nt = 0; nt < 8; nt++) {
        int col = nt * 8 + (l & 3) * 2;
        uint32_t hi, lo;
        split2pk(o[nt][0] * inv0, o[nt][1] * inv0, hi, lo);
        ((uint32_t*)Ahg)[(base0 + col) >> 1] = hi;
        ((uint32_t*)Alg)[(base0 + col) >> 1] = lo;
        split2pk(o[nt][2] * inv1, o[nt][3] * inv1, hi, lo);
        ((uint32_t*)Ahg)[(base1 + col) >> 1] = hi;
        ((uint32_t*)Alg)[(base1 + col) >> 1] = lo;
    }
}

// ---------------------------------------------------------------------------
extern "C" void kernel_launch(void* const* d_in, const int* in_sizes, int n_in,
                              void* d_out, int out_size)
{
    const float* hs = (const float*)d_in[0];
    const float* Wq = (const float*)d_in[1];
    const float* Wk = (const float*)d_in[2];
    const float* Wv = (const float*)d_in[3];
    const float* Wo = (const float*)d_in[4];
    float* out = (float*)d_out;

    bf16 *Xh, *Xl, *Wqh, *Wql, *Wkh, *Wkl, *Wvh, *Wvl, *Woh, *Wol;
    bf16 *Qh, *Ql, *Kh, *Kl, *Vh, *Vl, *Ahp, *Alp;
    cudaGetSymbolAddress((void**)&Xh, g_Xh);   cudaGetSymbolAddress((void**)&Xl, g_Xl);
    cudaGetSymbolAddress((void**)&Wqh, g_Wqh); cudaGetSymbolAddress((void**)&Wql, g_Wql);
    cudaGetSymbolAddress((void**)&Wkh, g_Wkh); cudaGetSymbolAddress((void**)&Wkl, g_Wkl);
    cudaGetSymbolAddress((void**)&Wvh, g_Wvh); cudaGetSymbolAddress((void**)&Wvl, g_Wvl);
    cudaGetSymbolAddress((void**)&Woh, g_Woh); cudaGetSymbolAddress((void**)&Wol, g_Wol);
    cudaGetSymbolAddress((void**)&Qh, g_Qh);   cudaGetSymbolAddress((void**)&Ql, g_Ql);
    cudaGetSymbolAddress((void**)&Kh, g_Kh);   cudaGetSymbolAddress((void**)&Kl, g_Kl);
    cudaGetSymbolAddress((void**)&Vh, g_Vh);   cudaGetSymbolAddress((void**)&Vl, g_Vl);
    cudaGetSymbolAddress((void**)&Ahp, g_Ah);  cudaGetSymbolAddress((void**)&Alp, g_Al);

    constexpr int STG128 = 2 * (128 * 64) + 2 * (32 * 128 * 2);  // 32768
    cudaFuncSetAttribute(qkv_proj, cudaFuncAttributeMaxDynamicSharedMemorySize, 2 * STG128);
    cudaFuncSetAttribute(o_proj,   cudaFuncAttributeMaxDynamicSharedMemorySize, 2 * STG128);
    cudaFuncSetAttribute(flash_bf, cudaFuncAttributeMaxDynamicSharedMemorySize, FSMEM);

    split_all<<<R_WO / 256, 256>>>(hs, Wq, Wk, Wv, Wo,
                                   Xh, Xl, Wqh, Wql, Wkh, Wkl, Wvh, Wvl, Woh, Wol);
    qkv_proj<<<dim3(10, MTOT / 128), 256, 2 * STG128>>>(
        Xh, Xl, Wqh, Wql, Wkh, Wkl, Wvh, Wvl, Qh, Ql, Kh, Kl, Vh, Vl);
    flash_bf<<<dim3(SEQ / QT, NHEAD, NB), 512, FSMEM>>>(Qh, Ql, Kh, Kl, Vh, Vl, Ahp, Alp);
    o_proj<<<dim3(HIDDIM / 128, MTOT / 128), 256, 2 * STG128>>>(Ahp, Alp, Woh, Wol, out);
}

// round 10
// speedup vs baseline: 1.6699x; 1.0532x over previous
#include <cuda_runtime.h>
#include <cuda_bf16.h>
#include <cstdint>

// ---------------------------------------------------------------------------
// MQA, split-bf16 mma.sync. R10: K/V projections fused into ONE 128-wide GEMM
// (concatenated [Wk|Wv] built in split_all) -> qkv grid 288 CTAs = 1 wave.
// ---------------------------------------------------------------------------
#define NB     2
#define SEQ    2048
#define HIDDIM 1024
#define NHEAD  16
#define HD     64
#define MTOT   (NB * SEQ)
#define QK_SCALE_LOG2E 0.180336880111120f   // 0.125 * log2(e)

typedef __nv_bfloat16 bf16;

__device__ bf16 g_Xh[MTOT * HIDDIM], g_Xl[MTOT * HIDDIM];
__device__ bf16 g_Wqh[HIDDIM * HIDDIM], g_Wql[HIDDIM * HIDDIM];
__device__ bf16 g_Wkvh[HIDDIM * 128],   g_Wkvl[HIDDIM * 128];   // [Wk|Wv]
__device__ bf16 g_Woh[HIDDIM * HIDDIM], g_Wol[HIDDIM * HIDDIM];
__device__ bf16 g_Qh[MTOT * HIDDIM], g_Ql[MTOT * HIDDIM];
__device__ bf16 g_KVh[MTOT * 128],   g_KVl[MTOT * 128];         // [K|V] per row
__device__ bf16 g_Ah[MTOT * HIDDIM], g_Al[MTOT * HIDDIM];

// ---------------- helpers ----------------
__device__ __forceinline__ uint32_t s2u(const void* p) {
    uint32_t a;
    asm("{ .reg .u64 t; cvta.to.shared.u64 t, %1; cvt.u32.u64 %0, t; }"
        : "=r"(a) : "l"(p));
    return a;
}
__device__ __forceinline__ void cpa16(uint32_t dst, const void* src) {
    asm volatile("cp.async.cg.shared.global [%0], [%1], 16;" :: "r"(dst), "l"(src));
}
#define CP_COMMIT() asm volatile("cp.async.commit_group;" ::: "memory")
#define CP_WAIT(n)  asm volatile("cp.async.wait_group %0;" :: "n"(n) : "memory")

__device__ __forceinline__ void ldm4(uint32_t* r, uint32_t a) {
    asm volatile("ldmatrix.sync.aligned.m8n8.x4.shared.b16 {%0,%1,%2,%3}, [%4];"
        : "=r"(r[0]), "=r"(r[1]), "=r"(r[2]), "=r"(r[3]) : "r"(a));
}
__device__ __forceinline__ void ldm4t(uint32_t* r, uint32_t a) {
    asm volatile("ldmatrix.sync.aligned.m8n8.x4.trans.shared.b16 {%0,%1,%2,%3}, [%4];"
        : "=r"(r[0]), "=r"(r[1]), "=r"(r[2]), "=r"(r[3]) : "r"(a));
}
__device__ __forceinline__ void mmabf(float* d, const uint32_t* a, const uint32_t* b) {
    asm volatile("mma.sync.aligned.m16n8k16.row.col.f32.bf16.bf16.f32 "
        "{%0,%1,%2,%3},{%4,%5,%6,%7},{%8,%9},{%0,%1,%2,%3};"
        : "+f"(d[0]), "+f"(d[1]), "+f"(d[2]), "+f"(d[3])
        : "r"(a[0]), "r"(a[1]), "r"(a[2]), "r"(a[3]), "r"(b[0]), "r"(b[1]));
}
__device__ __forceinline__ void split2pk(float a, float b, uint32_t& hi, uint32_t& lo) {
    __nv_bfloat16 ha = __float2bfloat16_rn(a), hb = __float2bfloat16_rn(b);
    float ra = a - __bfloat162float(ha), rb = b - __bfloat162float(hb);
    __nv_bfloat16 la = __float2bfloat16_rn(ra), lb = __float2bfloat16_rn(rb);
    hi = (uint32_t)__bfloat16_as_ushort(ha) | ((uint32_t)__bfloat16_as_ushort(hb) << 16);
    lo = (uint32_t)__bfloat16_as_ushort(la) | ((uint32_t)__bfloat16_as_ushort(lb) << 16);
}

// ---------------------------------------------------------------------------
// Fused split. Wk/Wv are interleaved into the [1024 x 128] fused KV weight.
// Region boundaries in float4 units.
// ---------------------------------------------------------------------------
#define R_X  1048576
#define R_WQ (R_X + 262144)
#define R_WK (R_WQ + 16384)
#define R_WV (R_WK + 16384)
#define R_WO (R_WV + 262144)

__global__ void split_all(const float* __restrict__ x,  const float* __restrict__ wq,
                          const float* __restrict__ wk, const float* __restrict__ wv,
                          const float* __restrict__ wo,
                          bf16* xh, bf16* xl, bf16* qh, bf16* ql,
                          bf16* kvh, bf16* kvl, bf16* oh, bf16* ol)
{
    int i = blockIdx.x * blockDim.x + threadIdx.x;
    if (i >= R_WO) return;
    const float* in; bf16 *hi, *lo; int j, o4;
    if (i < R_X)       { in = x;  hi = xh; lo = xl; j = i;        o4 = j; }
    else if (i < R_WQ) { in = wq; hi = qh; lo = ql; j = i - R_X;  o4 = j; }
    else if (i < R_WK) { in = wk; hi = kvh; lo = kvl; j = i - R_WQ;
                         o4 = ((j >> 4) << 5) + (j & 15); }          // k*32 + n/4
    else if (i < R_WV) { in = wv; hi = kvh; lo = kvl; j = i - R_WK;
                         o4 = ((j >> 4) << 5) + (j & 15) + 16; }     // +64 cols
    else               { in = wo; hi = oh; lo = ol; j = i - R_WV; o4 = j; }
    float4 v = ((const float4*)in)[j];
    uint32_t h0, l0, h1, l1;
    split2pk(v.x, v.y, h0, l0);
    split2pk(v.z, v.w, h1, l1);
    ((uint2*)hi)[o4] = make_uint2(h0, h1);
    ((uint2*)lo)[o4] = make_uint2(l0, l1);
}

// ---------------------------------------------------------------------------
// GEMM body: C[128 x NTILE] tile of A[M,K]*B[K,N]; cp.async 2-stage.
// ---------------------------------------------------------------------------
template<int NTILE, int EPI>
__device__ __forceinline__
void gemm_body(const bf16* __restrict__ Ah, const bf16* __restrict__ Al,
               const bf16* __restrict__ Bh, const bf16* __restrict__ Bl,
               float* __restrict__ Cf, bf16* __restrict__ Ch, bf16* __restrict__ Cl,
               int N, int K, float scale, int m0, int n0, char* smc)
{
    constexpr int ASZ = 128 * 64;
    constexpr int BSZ = 32 * NTILE * 2;
    constexpr int STG = 2 * ASZ + 2 * BSZ;
    constexpr int RB  = NTILE * 2;
    constexpr int NTT = NTILE / 32;

    const int tid = threadIdx.x, l = tid & 31, wid = tid >> 5;
    const int wm = (wid & 1) * 64, wn = (wid >> 1) * (NTILE / 4);
    const uint32_t sb = s2u(smc);

    float acc[4][NTT][4];
    #pragma unroll
    for (int i = 0; i < 4; i++)
        #pragma unroll
        for (int j = 0; j < NTT; j++)
            #pragma unroll
            for (int k = 0; k < 4; k++) acc[i][j][k] = 0.0f;

    auto load_chunk = [&](int kc, int s) {
        uint32_t st = sb + s * STG;
        #pragma unroll
        for (int i = 0; i < 2; i++) {
            int idx = tid + 256 * i;
            int r = idx >> 2, cq = idx & 3;
            uint32_t off = r * 64 + ((cq * 16) ^ ((r & 3) << 4));
            size_t src = (size_t)(m0 + r) * K + kc * 32 + cq * 8;
            cpa16(st + off, Ah + src);
            cpa16(st + ASZ + off, Al + src);
        }
        constexpr int BCH = BSZ / 16;
        constexpr int CPR = NTILE / 8;
        #pragma unroll
        for (int i = 0; i < (BCH + 255) / 256; i++) {
            int idx = tid + 256 * i;
            if (BCH < 256 || idx < BCH) {
                int r = idx / CPR, cq = idx % CPR;
                uint32_t off = 2 * ASZ + r * RB + ((cq * 16) ^ ((r & 7) << 4));
                size_t src = (size_t)(kc * 32 + r) * N + n0 + cq * 8;
                cpa16(st + off, Bh + src);
                cpa16(st + BSZ + off, Bl + src);
            }
        }
    };

    load_chunk(0, 0);
    CP_COMMIT();

    const int NC = K / 32;
    for (int kc = 0; kc < NC; kc++) {
        if (kc + 1 < NC) {
            load_chunk(kc + 1, (kc + 1) & 1);
            CP_COMMIT();
            CP_WAIT(1);
        } else {
            CP_WAIT(0);
        }
        __syncthreads();

        uint32_t st = sb + (kc & 1) * STG;
        #pragma unroll
        for (int ks = 0; ks < 2; ks++) {
            uint32_t af[2][4][4], bfr[2][NTT][2];
            #pragma unroll
            for (int mt = 0; mt < 4; mt++) {
                int row = wm + mt * 16 + (l & 15);
                uint32_t off = row * 64 + (((uint32_t)(ks * 32 + (l >> 4) * 16)) ^ ((row & 3) << 4));
                ldm4(af[0][mt], st + off);
                ldm4(af[1][mt], st + ASZ + off);
            }
            #pragma unroll
            for (int bg = 0; bg < NTT / 2; bg++) {
                int k = ks * 16 + (l & 7) + (((l >> 3) & 1) << 3);
                uint32_t byt = (uint32_t)((wn + bg * 16) * 2 + ((l >> 4) << 4));
                uint32_t off = 2 * ASZ + k * RB + (byt ^ ((k & 7) << 4));
                uint32_t t0[4], t1[4];
                ldm4t(t0, st + off);
                ldm4t(t1, st + BSZ + off);
                bfr[0][2*bg][0] = t0[0]; bfr[0][2*bg][1] = t0[1];
                bfr[0][2*bg+1][0] = t0[2]; bfr[0][2*bg+1][1] = t0[3];
                bfr[1][2*bg][0] = t1[0]; bfr[1][2*bg][1] = t1[1];
                bfr[1][2*bg+1][0] = t1[2]; bfr[1][2*bg+1][1] = t1[3];
            }
            #pragma unroll
            for (int mt = 0; mt < 4; mt++)
                #pragma unroll
                for (int nt = 0; nt < NTT; nt++) {
                    mmabf(acc[mt][nt], af[0][mt], bfr[0][nt]);
                    mmabf(acc[mt][nt], af[0][mt], bfr[1][nt]);
                    mmabf(acc[mt][nt], af[1][mt], bfr[0][nt]);
                }
        }
        __syncthreads();
    }

    #pragma unroll
    for (int mt = 0; mt < 4; mt++)
        #pragma unroll
        for (int nt = 0; nt < NTT; nt++) {
            int rg = m0 + wm + mt * 16 + (l >> 2);
            int cg = n0 + wn + nt * 8 + (l & 3) * 2;
            if (EPI == 0) {
                *(float2*)(Cf + (size_t)rg * N + cg)       = make_float2(acc[mt][nt][0], acc[mt][nt][1]);
                *(float2*)(Cf + (size_t)(rg + 8) * N + cg) = make_float2(acc[mt][nt][2], acc[mt][nt][3]);
            } else {
                uint32_t h0, l0, h1, l1;
                split2pk(acc[mt][nt][0] * scale, acc[mt][nt][1] * scale, h0, l0);
                split2pk(acc[mt][nt][2] * scale, acc[mt][nt][3] * scale, h1, l1);
                ((uint32_t*)Ch)[((size_t)rg * N + cg) >> 1] = h0;
                ((uint32_t*)Cl)[((size_t)rg * N + cg) >> 1] = l0;
                ((uint32_t*)Ch)[((size_t)(rg + 8) * N + cg) >> 1] = h1;
                ((uint32_t*)Cl)[((size_t)(rg + 8) * N + cg) >> 1] = l1;
            }
        }
}

// Merged Q + fused-KV projection: grid (9, 32) = 288 CTAs (single wave).
__global__ __launch_bounds__(256, 2)
void qkv_proj(const bf16* __restrict__ Xh, const bf16* __restrict__ Xl,
              const bf16* __restrict__ Wqh, const bf16* __restrict__ Wql,
              const bf16* __restrict__ Wkvh, const bf16* __restrict__ Wkvl,
              bf16* Qh, bf16* Ql, bf16* KVh, bf16* KVl)
{
    extern __shared__ char smc[];
    const int bx = blockIdx.x, m0 = blockIdx.y * 128;
    if (bx < 8) {
        gemm_body<128, 1>(Xh, Xl, Wqh, Wql, nullptr, Qh, Ql,
                          HIDDIM, HIDDIM, QK_SCALE_LOG2E, m0, bx * 128, smc);
    } else {
        gemm_body<128, 1>(Xh, Xl, Wkvh, Wkvl, nullptr, KVh, KVl,
                          128, HIDDIM, 1.0f, m0, 0, smc);
    }
}

__global__ __launch_bounds__(256, 2)
void o_proj(const bf16* __restrict__ Ahp, const bf16* __restrict__ Alp,
            const bf16* __restrict__ Woh, const bf16* __restrict__ Wol,
            float* __restrict__ out)
{
    extern __shared__ char smc[];
    gemm_body<128, 0>(Ahp, Alp, Woh, Wol, out, nullptr, nullptr,
                      HIDDIM, HIDDIM, 1.0f, blockIdx.y * 128, blockIdx.x * 128, smc);
}

// ---------------------------------------------------------------------------
// Flash attention: reads fused KV buffer (K at +0, V at +64 per 128-wide row).
// ---------------------------------------------------------------------------
#define FQH  0
#define FQL  32768
#define FKV  65536
#define FSMEM 196608
#define QT   256

__global__ __launch_bounds__(512, 1)
void flash_bf(const bf16* __restrict__ Qh, const bf16* __restrict__ Ql,
              const bf16* __restrict__ KVh, const bf16* __restrict__ KVl,
              bf16* __restrict__ Ahg, bf16* __restrict__ Alg)
{
    extern __shared__ char smc[];
    const uint32_t sb = s2u(smc);

    const int tid = threadIdx.x, l = tid & 31, wid = tid >> 5;
    const int q0 = blockIdx.x * QT, h = blockIdx.y, b = blockIdx.z;

    #pragma unroll
    for (int i = 0; i < 4; i++) {
        int idx = tid + 512 * i;
        int r = idx >> 3, cq = idx & 7;
        uint32_t off = r * 128 + ((cq * 16) ^ ((r & 7) << 4));
        size_t src = (size_t)(b * SEQ + q0 + r) * HIDDIM + h * HD + cq * 8;
        cpa16(sb + FQH + off, Qh + src);
        cpa16(sb + FQL + off, Ql + src);
    }
    #pragma unroll
    for (int i = 0; i < 2; i++) {
        int idx = tid + 512 * i;
        int r = idx >> 3, cq = idx & 7;
        uint32_t off = r * 128 + ((cq * 16) ^ ((r & 7) << 4));
        size_t srcK = (size_t)(b * SEQ + r) * 128 + cq * 8;
        cpa16(sb + FKV + off,         KVh + srcK);
        cpa16(sb + FKV + 16384 + off, KVl + srcK);
        cpa16(sb + FKV + 32768 + off, KVh + srcK + 64);
        cpa16(sb + FKV + 49152 + off, KVl + srcK + 64);
    }
    CP_COMMIT();

    uint32_t qf[2][4][4];
    float o[8][4];
    #pragma unroll
    for (int i = 0; i < 8; i++)
        #pragma unroll
        for (int k = 0; k < 4; k++) o[i][k] = 0.0f;
    float preg[2] = {0.0f, 0.0f};

    for (int t = 0; t < 16; t++) {
        if (t < 15) {
            uint32_t st = sb + FKV + ((t + 1) & 1) * 65536;
            #pragma unroll
            for (int i = 0; i < 2; i++) {
                int idx = tid + 512 * i;
                int r = idx >> 3, cq = idx & 7;
                uint32_t off = r * 128 + ((cq * 16) ^ ((r & 7) << 4));
                size_t srcK = (size_t)(b * SEQ + (t + 1) * 128 + r) * 128 + cq * 8;
                cpa16(st + off,         KVh + srcK);
                cpa16(st + 16384 + off, KVl + srcK);
                cpa16(st + 32768 + off, KVh + srcK + 64);
                cpa16(st + 49152 + off, KVl + srcK + 64);
            }
            CP_COMMIT();
            CP_WAIT(1);
        } else {
            CP_WAIT(0);
        }
        __syncthreads();

        if (t == 0) {
            #pragma unroll
            for (int ks = 0; ks < 4; ks++) {
                int row = wid * 16 + (l & 15);
                uint32_t off = row * 128 + (((uint32_t)(ks * 32 + (l >> 4) * 16)) ^ ((row & 7) << 4));
                ldm4(qf[0][ks], sb + FQH + off);
                ldm4(qf[1][ks], sb + FQL + off);
            }
        }

        const uint32_t stK = sb + FKV + (t & 1) * 65536;
        const uint32_t stV = stK + 32768;

        #pragma unroll
        for (int g = 0; g < 8; g++) {
            float sA[2][4], sB[2][4];
            #pragma unroll
            for (int i = 0; i < 2; i++)
                #pragma unroll
                for (int k = 0; k < 4; k++) { sA[i][k] = 0.0f; sB[i][k] = 0.0f; }

            int krow = g * 16 + (l & 7) + ((l >> 4) << 3);
            #pragma unroll
            for (int ks = 0; ks < 4; ks++) {
                uint32_t off = krow * 128 + (((uint32_t)(ks * 32 + ((l >> 3) & 1) * 16)) ^ ((krow & 7) << 4));
                uint32_t t0[4], t1[4];
                ldm4(t0, stK + off);
                ldm4(t1, stK + 16384 + off);
                uint32_t bh0[2] = {t0[0], t0[1]}, bh1[2] = {t0[2], t0[3]};
                uint32_t bl0[2] = {t1[0], t1[1]}, bl1[2] = {t1[2], t1[3]};
                mmabf(sA[0], qf[0][ks], bh0);
                mmabf(sB[0], qf[0][ks], bl0);
                mmabf(sA[1], qf[0][ks], bh1);
                mmabf(sB[1], qf[0][ks], bl1);
                mmabf(sA[0], qf[1][ks], bh0);
                mmabf(sA[1], qf[1][ks], bh1);
            }

            float s2[2][4];
            #pragma unroll
            for (int i = 0; i < 2; i++) {
                #pragma unroll
                for (int k = 0; k < 4; k++)
                    s2[i][k] = exp2f(sA[i][k] + sB[i][k]);
                preg[0] += s2[i][0] + s2[i][1];
                preg[1] += s2[i][2] + s2[i][3];
            }

            uint32_t aH[4], aL[4];
            split2pk(s2[0][0], s2[0][1], aH[0], aL[0]);
            split2pk(s2[0][2], s2[0][3], aH[1], aL[1]);
            split2pk(s2[1][0], s2[1][1], aH[2], aL[2]);
            split2pk(s2[1][2], s2[1][3], aH[3], aL[3]);

            int key = g * 16 + (l & 7) + (((l >> 3) & 1) << 3);
            #pragma unroll
            for (int bg = 0; bg < 4; bg++) {
                uint32_t byt = (uint32_t)(bg * 32 + ((l >> 4) << 4));
                uint32_t off = key * 128 + (byt ^ ((key & 7) << 4));
                uint32_t t0[4], t1[4];
                ldm4t(t0, stV + off);
                ldm4t(t1, stV + 16384 + off);
                uint32_t bh0[2] = {t0[0], t0[1]}, bh1[2] = {t0[2], t0[3]};
                uint32_t bl0[2] = {t1[0], t1[1]}, bl1[2] = {t1[2], t1[3]};
                mmabf(o[2*bg],   aH, bh0);
                mmabf(o[2*bg],   aH, bl0);
                mmabf(o[2*bg],   aL, bh0);
                mmabf(o[2*bg+1], aH, bh1);
                mmabf(o[2*bg+1], aH, bl1);
                mmabf(o[2*bg+1], aL, bh1);
            }
        }
        __syncthreads();
    }

    #pragma unroll
    for (int i = 0; i < 2; i++) {
        preg[i] += __shfl_xor_sync(0xffffffffu, preg[i], 1);
        preg[i] += __shfl_xor_sync(0xffffffffu, preg[i], 2);
    }
    float inv0 = 1.0f / preg[0], inv1 = 1.0f / preg[1];

    int r0 = wid * 16 + (l >> 2);
    size_t base0 = (size_t)(b * SEQ + q0 + r0) * HIDDIM + h * HD;
    size_t base1 = (size_t)(b * SEQ + q0 + r0 + 8) * HIDDIM + h * HD;
    #pragma unroll
    for (int nt = 0; nt < 8; nt++) {
        int col = nt * 8 + (l & 3) * 2;
        uint32_t hi, lo;
        split2pk(o[nt][0] * inv0, o[nt][1] * inv0, hi, lo);
        ((uint32_t*)Ahg)[(base0 + col) >> 1] = hi;
        ((uint32_t*)Alg)[(base0 + col) >> 1] = lo;
        split2pk(o[nt][2] * inv1, o[nt][3] * inv1, hi, lo);
        ((uint32_t*)Ahg)[(base1 + col) >> 1] = hi;
        ((uint32_t*)Alg)[(base1 + col) >> 1] = lo;
    }
}

// ---------------------------------------------------------------------------
extern "C" void kernel_launch(void* const* d_in, const int* in_sizes, int n_in,
                              void* d_out, int out_size)
{
    const float* hs = (const float*)d_in[0];
    const float* Wq = (const float*)d_in[1];
    const float* Wk = (const float*)d_in[2];
    const float* Wv = (const float*)d_in[3];
    const float* Wo = (const float*)d_in[4];
    float* out = (float*)d_out;

    bf16 *Xh, *Xl, *Wqh, *Wql, *Wkvh, *Wkvl, *Woh, *Wol;
    bf16 *Qh, *Ql, *KVh, *KVl, *Ahp, *Alp;
    cudaGetSymbolAddress((void**)&Xh, g_Xh);     cudaGetSymbolAddress((void**)&Xl, g_Xl);
    cudaGetSymbolAddress((void**)&Wqh, g_Wqh);   cudaGetSymbolAddress((void**)&Wql, g_Wql);
    cudaGetSymbolAddress((void**)&Wkvh, g_Wkvh); cudaGetSymbolAddress((void**)&Wkvl, g_Wkvl);
    cudaGetSymbolAddress((void**)&Woh, g_Woh);   cudaGetSymbolAddress((void**)&Wol, g_Wol);
    cudaGetSymbolAddress((void**)&Qh, g_Qh);     cudaGetSymbolAddress((void**)&Ql, g_Ql);
    cudaGetSymbolAddress((void**)&KVh, g_KVh);   cudaGetSymbolAddress((void**)&KVl, g_KVl);
    cudaGetSymbolAddress((void**)&Ahp, g_Ah);    cudaGetSymbolAddress((void**)&Alp, g_Al);

    constexpr int STG128 = 2 * (128 * 64) + 2 * (32 * 128 * 2);  // 32768
    cudaFuncSetAttribute(qkv_proj, cudaFuncAttributeMaxDynamicSharedMemorySize, 2 * STG128);
    cudaFuncSetAttribute(o_proj,   cudaFuncAttributeMaxDynamicSharedMemorySize, 2 * STG128);
    cudaFuncSetAttribute(flash_bf, cudaFuncAttributeMaxDynamicSharedMemorySize, FSMEM);

    split_all<<<(R_WO + 255) / 256, 256>>>(hs, Wq, Wk, Wv, Wo,
                                           Xh, Xl, Wqh, Wql, Wkvh, Wkvl, Woh, Wol);
    qkv_proj<<<dim3(9, MTOT / 128), 256, 2 * STG128>>>(
        Xh, Xl, Wqh, Wql, Wkvh, Wkvl, Qh, Ql, KVh, KVl);
    flash_bf<<<dim3(SEQ / QT, NHEAD, NB), 512, FSMEM>>>(Qh, Ql, KVh, KVl, Ahp, Alp);
    o_proj<<<dim3(HIDDIM / 128, MTOT / 128), 256, 2 * STG128>>>(Ahp, Alp, Woh, Wol, out);
}

// round 12
// speedup vs baseline: 1.6885x; 1.0111x over previous
#include <cuda_runtime.h>
#include <cuda_bf16.h>
#include <cstdint>

// ---------------------------------------------------------------------------
// MQA, split-bf16 mma.sync. R11: 3-stage cp.async pipelines, single sync per
// chunk/tile (CUTLASS wait->sync->issue order). Flash reuses dead Q smem as
// third KV stage.
// ---------------------------------------------------------------------------
#define NB     2
#define SEQ    2048
#define HIDDIM 1024
#define NHEAD  16
#define HD     64
#define MTOT   (NB * SEQ)
#define QK_SCALE_LOG2E 0.180336880111120f   // 0.125 * log2(e)

typedef __nv_bfloat16 bf16;

__device__ bf16 g_Xh[MTOT * HIDDIM], g_Xl[MTOT * HIDDIM];
__device__ bf16 g_Wqh[HIDDIM * HIDDIM], g_Wql[HIDDIM * HIDDIM];
__device__ bf16 g_Wkvh[HIDDIM * 128],   g_Wkvl[HIDDIM * 128];   // [Wk|Wv]
__device__ bf16 g_Woh[HIDDIM * HIDDIM], g_Wol[HIDDIM * HIDDIM];
__device__ bf16 g_Qh[MTOT * HIDDIM], g_Ql[MTOT * HIDDIM];
__device__ bf16 g_KVh[MTOT * 128],   g_KVl[MTOT * 128];         // [K|V] per row
__device__ bf16 g_Ah[MTOT * HIDDIM], g_Al[MTOT * HIDDIM];

// ---------------- helpers ----------------
__device__ __forceinline__ uint32_t s2u(const void* p) {
    uint32_t a;
    asm("{ .reg .u64 t; cvta.to.shared.u64 t, %1; cvt.u32.u64 %0, t; }"
        : "=r"(a) : "l"(p));
    return a;
}
__device__ __forceinline__ void cpa16(uint32_t dst, const void* src) {
    asm volatile("cp.async.cg.shared.global [%0], [%1], 16;" :: "r"(dst), "l"(src));
}
#define CP_COMMIT() asm volatile("cp.async.commit_group;" ::: "memory")
#define CP_WAIT(n)  asm volatile("cp.async.wait_group %0;" :: "n"(n) : "memory")

__device__ __forceinline__ void ldm4(uint32_t* r, uint32_t a) {
    asm volatile("ldmatrix.sync.aligned.m8n8.x4.shared.b16 {%0,%1,%2,%3}, [%4];"
        : "=r"(r[0]), "=r"(r[1]), "=r"(r[2]), "=r"(r[3]) : "r"(a));
}
__device__ __forceinline__ void ldm4t(uint32_t* r, uint32_t a) {
    asm volatile("ldmatrix.sync.aligned.m8n8.x4.trans.shared.b16 {%0,%1,%2,%3}, [%4];"
        : "=r"(r[0]), "=r"(r[1]), "=r"(r[2]), "=r"(r[3]) : "r"(a));
}
__device__ __forceinline__ void mmabf(float* d, const uint32_t* a, const uint32_t* b) {
    asm volatile("mma.sync.aligned.m16n8k16.row.col.f32.bf16.bf16.f32 "
        "{%0,%1,%2,%3},{%4,%5,%6,%7},{%8,%9},{%0,%1,%2,%3};"
        : "+f"(d[0]), "+f"(d[1]), "+f"(d[2]), "+f"(d[3])
        : "r"(a[0]), "r"(a[1]), "r"(a[2]), "r"(a[3]), "r"(b[0]), "r"(b[1]));
}
__device__ __forceinline__ void split2pk(float a, float b, uint32_t& hi, uint32_t& lo) {
    __nv_bfloat16 ha = __float2bfloat16_rn(a), hb = __float2bfloat16_rn(b);
    float ra = a - __bfloat162float(ha), rb = b - __bfloat162float(hb);
    __nv_bfloat16 la = __float2bfloat16_rn(ra), lb = __float2bfloat16_rn(rb);
    hi = (uint32_t)__bfloat16_as_ushort(ha) | ((uint32_t)__bfloat16_as_ushort(hb) << 16);
    lo = (uint32_t)__bfloat16_as_ushort(la) | ((uint32_t)__bfloat16_as_ushort(lb) << 16);
}

// ---------------------------------------------------------------------------
// Fused split. Wk/Wv interleave into the [1024 x 128] fused KV weight.
// ---------------------------------------------------------------------------
#define R_X  1048576
#define R_WQ (R_X + 262144)
#define R_WK (R_WQ + 16384)
#define R_WV (R_WK + 16384)
#define R_WO (R_WV + 262144)

__global__ void split_all(const float* __restrict__ x,  const float* __restrict__ wq,
                          const float* __restrict__ wk, const float* __restrict__ wv,
                          const float* __restrict__ wo,
                          bf16* xh, bf16* xl, bf16* qh, bf16* ql,
                          bf16* kvh, bf16* kvl, bf16* oh, bf16* ol)
{
    int i = blockIdx.x * blockDim.x + threadIdx.x;
    if (i >= R_WO) return;
    const float* in; bf16 *hi, *lo; int j, o4;
    if (i < R_X)       { in = x;  hi = xh; lo = xl; j = i;        o4 = j; }
    else if (i < R_WQ) { in = wq; hi = qh; lo = ql; j = i - R_X;  o4 = j; }
    else if (i < R_WK) { in = wk; hi = kvh; lo = kvl; j = i - R_WQ;
                         o4 = ((j >> 4) << 5) + (j & 15); }
    else if (i < R_WV) { in = wv; hi = kvh; lo = kvl; j = i - R_WK;
                         o4 = ((j >> 4) << 5) + (j & 15) + 16; }
    else               { in = wo; hi = oh; lo = ol; j = i - R_WV; o4 = j; }
    float4 v = ((const float4*)in)[j];
    uint32_t h0, l0, h1, l1;
    split2pk(v.x, v.y, h0, l0);
    split2pk(v.z, v.w, h1, l1);
    ((uint2*)hi)[o4] = make_uint2(h0, h1);
    ((uint2*)lo)[o4] = make_uint2(l0, l1);
}

// ---------------------------------------------------------------------------
// GEMM body: 3-stage cp.async pipeline, ONE __syncthreads per k-chunk.
// ---------------------------------------------------------------------------
template<int NTILE, int EPI>
__device__ __forceinline__
void gemm_body(const bf16* __restrict__ Ah, const bf16* __restrict__ Al,
               const bf16* __restrict__ Bh, const bf16* __restrict__ Bl,
               float* __restrict__ Cf, bf16* __restrict__ Ch, bf16* __restrict__ Cl,
               int N, int K, float scale, int m0, int n0, char* smc)
{
    constexpr int ASZ = 128 * 64;
    constexpr int BSZ = 32 * NTILE * 2;
    constexpr int STG = 2 * ASZ + 2 * BSZ;
    constexpr int RB  = NTILE * 2;
    constexpr int NTT = NTILE / 32;

    const int tid = threadIdx.x, l = tid & 31, wid = tid >> 5;
    const int wm = (wid & 1) * 64, wn = (wid >> 1) * (NTILE / 4);
    const uint32_t sb = s2u(smc);

    float acc[4][NTT][4];
    #pragma unroll
    for (int i = 0; i < 4; i++)
        #pragma unroll
        for (int j = 0; j < NTT; j++)
            #pragma unroll
            for (int k = 0; k < 4; k++) acc[i][j][k] = 0.0f;

    auto load_chunk = [&](int kc, int s) {
        uint32_t st = sb + (uint32_t)s * STG;
        #pragma unroll
        for (int i = 0; i < 2; i++) {
            int idx = tid + 256 * i;
            int r = idx >> 2, cq = idx & 3;
            uint32_t off = r * 64 + ((cq * 16) ^ ((r & 3) << 4));
            size_t src = (size_t)(m0 + r) * K + kc * 32 + cq * 8;
            cpa16(st + off, Ah + src);
            cpa16(st + ASZ + off, Al + src);
        }
        constexpr int BCH = BSZ / 16;
        constexpr int CPR = NTILE / 8;
        #pragma unroll
        for (int i = 0; i < (BCH + 255) / 256; i++) {
            int idx = tid + 256 * i;
            if (BCH < 256 || idx < BCH) {
                int r = idx / CPR, cq = idx % CPR;
                uint32_t off = 2 * ASZ + r * RB + ((cq * 16) ^ ((r & 7) << 4));
                size_t src = (size_t)(kc * 32 + r) * N + n0 + cq * 8;
                cpa16(st + off, Bh + src);
                cpa16(st + BSZ + off, Bl + src);
            }
        }
    };

    load_chunk(0, 0); CP_COMMIT();
    load_chunk(1, 1); CP_COMMIT();

    const int NC = K / 32;
    for (int kc = 0; kc < NC; kc++) {
        if (kc + 1 < NC) { CP_WAIT(1); } else { CP_WAIT(0); }
        __syncthreads();     // data for kc visible; all warps done with kc-1
        if (kc + 2 < NC) { load_chunk(kc + 2, (kc + 2) % 3); CP_COMMIT(); }

        uint32_t st = sb + (uint32_t)(kc % 3) * STG;
        #pragma unroll
        for (int ks = 0; ks < 2; ks++) {
            uint32_t af[2][4][4], bfr[2][NTT][2];
            #pragma unroll
            for (int mt = 0; mt < 4; mt++) {
                int row = wm + mt * 16 + (l & 15);
                uint32_t off = row * 64 + (((uint32_t)(ks * 32 + (l >> 4) * 16)) ^ ((row & 3) << 4));
                ldm4(af[0][mt], st + off);
                ldm4(af[1][mt], st + ASZ + off);
            }
            #pragma unroll
            for (int bg = 0; bg < NTT / 2; bg++) {
                int k = ks * 16 + (l & 7) + (((l >> 3) & 1) << 3);
                uint32_t byt = (uint32_t)((wn + bg * 16) * 2 + ((l >> 4) << 4));
                uint32_t off = 2 * ASZ + k * RB + (byt ^ ((k & 7) << 4));
                uint32_t t0[4], t1[4];
                ldm4t(t0, st + off);
                ldm4t(t1, st + BSZ + off);
                bfr[0][2*bg][0] = t0[0]; bfr[0][2*bg][1] = t0[1];
                bfr[0][2*bg+1][0] = t0[2]; bfr[0][2*bg+1][1] = t0[3];
                bfr[1][2*bg][0] = t1[0]; bfr[1][2*bg][1] = t1[1];
                bfr[1][2*bg+1][0] = t1[2]; bfr[1][2*bg+1][1] = t1[3];
            }
            #pragma unroll
            for (int mt = 0; mt < 4; mt++)
                #pragma unroll
                for (int nt = 0; nt < NTT; nt++) {
                    mmabf(acc[mt][nt], af[0][mt], bfr[0][nt]);
                    mmabf(acc[mt][nt], af[0][mt], bfr[1][nt]);
                    mmabf(acc[mt][nt], af[1][mt], bfr[0][nt]);
                }
        }
    }

    #pragma unroll
    for (int mt = 0; mt < 4; mt++)
        #pragma unroll
        for (int nt = 0; nt < NTT; nt++) {
            int rg = m0 + wm + mt * 16 + (l >> 2);
            int cg = n0 + wn + nt * 8 + (l & 3) * 2;
            if (EPI == 0) {
                *(float2*)(Cf + (size_t)rg * N + cg)       = make_float2(acc[mt][nt][0], acc[mt][nt][1]);
                *(float2*)(Cf + (size_t)(rg + 8) * N + cg) = make_float2(acc[mt][nt][2], acc[mt][nt][3]);
            } else {
                uint32_t h0, l0, h1, l1;
                split2pk(acc[mt][nt][0] * scale, acc[mt][nt][1] * scale, h0, l0);
                split2pk(acc[mt][nt][2] * scale, acc[mt][nt][3] * scale, h1, l1);
                ((uint32_t*)Ch)[((size_t)rg * N + cg) >> 1] = h0;
                ((uint32_t*)Cl)[((size_t)rg * N + cg) >> 1] = l0;
                ((uint32_t*)Ch)[((size_t)(rg + 8) * N + cg) >> 1] = h1;
                ((uint32_t*)Cl)[((size_t)(rg + 8) * N + cg) >> 1] = l1;
            }
        }
}

// Merged Q + fused-KV projection: grid (9, 32) = 288 CTAs (single wave).
__global__ __launch_bounds__(256, 2)
void qkv_proj(const bf16* __restrict__ Xh, const bf16* __restrict__ Xl,
              const bf16* __restrict__ Wqh, const bf16* __restrict__ Wql,
              const bf16* __restrict__ Wkvh, const bf16* __restrict__ Wkvl,
              bf16* Qh, bf16* Ql, bf16* KVh, bf16* KVl)
{
    extern __shared__ char smc[];
    const int bx = blockIdx.x, m0 = blockIdx.y * 128;
    if (bx < 8) {
        gemm_body<128, 1>(Xh, Xl, Wqh, Wql, nullptr, Qh, Ql,
                          HIDDIM, HIDDIM, QK_SCALE_LOG2E, m0, bx * 128, smc);
    } else {
        gemm_body<128, 1>(Xh, Xl, Wkvh, Wkvl, nullptr, KVh, KVl,
                          128, HIDDIM, 1.0f, m0, 0, smc);
    }
}

__global__ __launch_bounds__(256, 2)
void o_proj(const bf16* __restrict__ Ahp, const bf16* __restrict__ Alp,
            const bf16* __restrict__ Woh, const bf16* __restrict__ Wol,
            float* __restrict__ out)
{
    extern __shared__ char smc[];
    gemm_body<128, 0>(Ahp, Alp, Woh, Wol, out, nullptr, nullptr,
                      HIDDIM, HIDDIM, 1.0f, blockIdx.y * 128, blockIdx.x * 128, smc);
}

// ---------------------------------------------------------------------------
// Flash attention: 3-stage KV pipeline. Stage 2 REUSES the Q smem region
// (dead after qf fragments load at t==0). One __syncthreads per tile.
// smem layout: [0,64K) Q hi/lo (-> KV stage 2) | [64K,128K) stage 0 | [128K,192K) stage 1
// ---------------------------------------------------------------------------
#define FSMEM 196608
#define QT    256
#define NTKV  16

__device__ __forceinline__ uint32_t kv_stage_off(int m3) {
    return (m3 == 0) ? 65536u : ((m3 == 1) ? 131072u : 0u);
}

__global__ __launch_bounds__(512, 1)
void flash_bf(const bf16* __restrict__ Qh, const bf16* __restrict__ Ql,
              const bf16* __restrict__ KVh, const bf16* __restrict__ KVl,
              bf16* __restrict__ Ahg, bf16* __restrict__ Alg)
{
    extern __shared__ char smc[];
    const uint32_t sb = s2u(smc);

    const int tid = threadIdx.x, l = tid & 31, wid = tid >> 5;
    const int q0 = blockIdx.x * QT, h = blockIdx.y, b = blockIdx.z;

    auto load_kv = [&](int t, uint32_t stoff) {
        uint32_t st = sb + stoff;
        #pragma unroll
        for (int i = 0; i < 2; i++) {
            int idx = tid + 512 * i;
            int r = idx >> 3, cq = idx & 7;
            uint32_t off = r * 128 + ((cq * 16) ^ ((r & 7) << 4));
            size_t srcK = (size_t)(b * SEQ + t * 128 + r) * 128 + cq * 8;
            cpa16(st + off,         KVh + srcK);
            cpa16(st + 16384 + off, KVl + srcK);
            cpa16(st + 32768 + off, KVh + srcK + 64);
            cpa16(st + 49152 + off, KVl + srcK + 64);
        }
    };

    // prologue: Q tile + KV tile 0 (group 0), KV tile 1 (group 1)
    #pragma unroll
    for (int i = 0; i < 4; i++) {
        int idx = tid + 512 * i;
        int r = idx >> 3, cq = idx & 7;
        uint32_t off = r * 128 + ((cq * 16) ^ ((r & 7) << 4));
        size_t src = (size_t)(b * SEQ + q0 + r) * HIDDIM + h * HD + cq * 8;
        cpa16(sb + off,         Qh + src);
        cpa16(sb + 32768 + off, Ql + src);
    }
    load_kv(0, 65536u);
    CP_COMMIT();
    load_kv(1, 131072u);
    CP_COMMIT();

    uint32_t qf[2][4][4];
    float o[8][4];
    #pragma unroll
    for (int i = 0; i < 8; i++)
        #pragma unroll
        for (int k = 0; k < 4; k++) o[i][k] = 0.0f;
    float preg[2] = {0.0f, 0.0f};

    for (int t = 0; t < NTKV; t++) {
        if (t + 1 < NTKV) { CP_WAIT(1); } else { CP_WAIT(0); }
        __syncthreads();     // tile t data visible; all warps done with t-1

        if (t == 0) {        // Q fragments once; then Q smem becomes stage 2
            #pragma unroll
            for (int ks = 0; ks < 4; ks++) {
                int row = wid * 16 + (l & 15);
                uint32_t off = row * 128 + (((uint32_t)(ks * 32 + (l >> 4) * 16)) ^ ((row & 7) << 4));
                ldm4(qf[0][ks], sb + off);
                ldm4(qf[1][ks], sb + 32768 + off);
            }
            __syncthreads(); // all qf reads done before stage-2 writes
        }

        if (t + 2 < NTKV) { load_kv(t + 2, kv_stage_off((t + 2) % 3)); CP_COMMIT(); }

        const uint32_t stK = sb + kv_stage_off(t % 3);
        const uint32_t stV = stK + 32768;

        #pragma unroll
        for (int g = 0; g < 8; g++) {
            float sA[2][4], sB[2][4];
            #pragma unroll
            for (int i = 0; i < 2; i++)
                #pragma unroll
                for (int k = 0; k < 4; k++) { sA[i][k] = 0.0f; sB[i][k] = 0.0f; }

            int krow = g * 16 + (l & 7) + ((l >> 4) << 3);
            #pragma unroll
            for (int ks = 0; ks < 4; ks++) {
                uint32_t off = krow * 128 + (((uint32_t)(ks * 32 + ((l >> 3) & 1) * 16)) ^ ((krow & 7) << 4));
                uint32_t t0[4], t1[4];
                ldm4(t0, stK + off);
                ldm4(t1, stK + 16384 + off);
                uint32_t bh0[2] = {t0[0], t0[1]}, bh1[2] = {t0[2], t0[3]};
                uint32_t bl0[2] = {t1[0], t1[1]}, bl1[2] = {t1[2], t1[3]};
                mmabf(sA[0], qf[0][ks], bh0);
                mmabf(sB[0], qf[0][ks], bl0);
                mmabf(sA[1], qf[0][ks], bh1);
                mmabf(sB[1], qf[0][ks], bl1);
                mmabf(sA[0], qf[1][ks], bh0);
                mmabf(sA[1], qf[1][ks], bh1);
            }

            float s2[2][4];
            #pragma unroll
            for (int i = 0; i < 2; i++) {
                #pragma unroll
                for (int k = 0; k < 4; k++)
                    s2[i][k] = exp2f(sA[i][k] + sB[i][k]);
                preg[0] += s2[i][0] + s2[i][1];
                preg[1] += s2[i][2] + s2[i][3];
            }

            uint32_t aH[4], aL[4];
            split2pk(s2[0][0], s2[0][1], aH[0], aL[0]);
            split2pk(s2[0][2], s2[0][3], aH[1], aL[1]);
            split2pk(s2[1][0], s2[1][1], aH[2], aL[2]);
            split2pk(s2[1][2], s2[1][3], aH[3], aL[3]);

            int key = g * 16 + (l & 7) + (((l >> 3) & 1) << 3);
            #pragma unroll
            for (int bg = 0; bg < 4; bg++) {
                uint32_t byt = (uint32_t)(bg * 32 + ((l >> 4) << 4));
                uint32_t off = key * 128 + (byt ^ ((key & 7) << 4));
                uint32_t t0[4], t1[4];
                ldm4t(t0, stV + off);
                ldm4t(t1, stV + 16384 + off);
                uint32_t bh0[2] = {t0[0], t0[1]}, bh1[2] = {t0[2], t0[3]};
                uint32_t bl0[2] = {t1[0], t1[1]}, bl1[2] = {t1[2], t1[3]};
                mmabf(o[2*bg],   aH, bh0);
                mmabf(o[2*bg],   aH, bl0);
                mmabf(o[2*bg],   aL, bh0);
                mmabf(o[2*bg+1], aH, bh1);
                mmabf(o[2*bg+1], aH, bl1);
                mmabf(o[2*bg+1], aL, bh1);
            }
        }
    }

    #pragma unroll
    for (int i = 0; i < 2; i++) {
        preg[i] += __shfl_xor_sync(0xffffffffu, preg[i], 1);
        preg[i] += __shfl_xor_sync(0xffffffffu, preg[i], 2);
    }
    float inv0 = 1.0f / preg[0], inv1 = 1.0f / preg[1];

    int r0 = wid * 16 + (l >> 2);
    size_t base0 = (size_t)(b * SEQ + q0 + r0) * HIDDIM + h * HD;
    size_t base1 = (size_t)(b * SEQ + q0 + r0 + 8) * HIDDIM + h * HD;
    #pragma unroll
    for (int nt = 0; nt < 8; nt++) {
        int col = nt * 8 + (l & 3) * 2;
        uint32_t hi, lo;
        split2pk(o[nt][0] * inv0, o[nt][1] * inv0, hi, lo);
        ((uint32_t*)Ahg)[(base0 + col) >> 1] = hi;
        ((uint32_t*)Alg)[(base0 + col) >> 1] = lo;
        split2pk(o[nt][2] * inv1, o[nt][3] * inv1, hi, lo);
        ((uint32_t*)Ahg)[(base1 + col) >> 1] = hi;
        ((uint32_t*)Alg)[(base1 + col) >> 1] = lo;
    }
}

// ---------------------------------------------------------------------------
extern "C" void kernel_launch(void* const* d_in, const int* in_sizes, int n_in,
                              void* d_out, int out_size)
{
    const float* hs = (const float*)d_in[0];
    const float* Wq = (const float*)d_in[1];
    const float* Wk = (const float*)d_in[2];
    const float* Wv = (const float*)d_in[3];
    const float* Wo = (const float*)d_in[4];
    float* out = (float*)d_out;

    bf16 *Xh, *Xl, *Wqh, *Wql, *Wkvh, *Wkvl, *Woh, *Wol;
    bf16 *Qh, *Ql, *KVh, *KVl, *Ahp, *Alp;
    cudaGetSymbolAddress((void**)&Xh, g_Xh);     cudaGetSymbolAddress((void**)&Xl, g_Xl);
    cudaGetSymbolAddress((void**)&Wqh, g_Wqh);   cudaGetSymbolAddress((void**)&Wql, g_Wql);
    cudaGetSymbolAddress((void**)&Wkvh, g_Wkvh); cudaGetSymbolAddress((void**)&Wkvl, g_Wkvl);
    cudaGetSymbolAddress((void**)&Woh, g_Woh);   cudaGetSymbolAddress((void**)&Wol, g_Wol);
    cudaGetSymbolAddress((void**)&Qh, g_Qh);     cudaGetSymbolAddress((void**)&Ql, g_Ql);
    cudaGetSymbolAddress((void**)&KVh, g_KVh);   cudaGetSymbolAddress((void**)&KVl, g_KVl);
    cudaGetSymbolAddress((void**)&Ahp, g_Ah);    cudaGetSymbolAddress((void**)&Alp, g_Al);

    constexpr int STG128 = 2 * (128 * 64) + 2 * (32 * 128 * 2);  // 32768 per stage
    cudaFuncSetAttribute(qkv_proj, cudaFuncAttributeMaxDynamicSharedMemorySize, 3 * STG128);
    cudaFuncSetAttribute(o_proj,   cudaFuncAttributeMaxDynamicSharedMemorySize, 3 * STG128);
    cudaFuncSetAttribute(flash_bf, cudaFuncAttributeMaxDynamicSharedMemorySize, FSMEM);

    split_all<<<(R_WO + 255) / 256, 256>>>(hs, Wq, Wk, Wv, Wo,
                                           Xh, Xl, Wqh, Wql, Wkvh, Wkvl, Woh, Wol);
    qkv_proj<<<dim3(9, MTOT / 128), 256, 3 * STG128>>>(
        Xh, Xl, Wqh, Wql, Wkvh, Wkvl, Qh, Ql, KVh, KVl);
    flash_bf<<<dim3(SEQ / QT, NHEAD, NB), 512, FSMEM>>>(Qh, Ql, KVh, KVl, Ahp, Alp);
    o_proj<<<dim3(HIDDIM / 128, MTOT / 128), 256, 3 * STG128>>>(Ahp, Alp, Woh, Wol, out);
}

// round 13
// speedup vs baseline: 1.7118x; 1.0138x over previous
#include <cuda_runtime.h>
#include <cuda_bf16.h>
#include <cstdint>

// ---------------------------------------------------------------------------
// MQA, split-bf16 mma.sync. R13: instruction diet — ex2.approx for softmax,
// cvt.bf16x2-based split2pk (6 ops vs ~14). Structure identical to R11.
// ---------------------------------------------------------------------------
#define NB     2
#define SEQ    2048
#define HIDDIM 1024
#define NHEAD  16
#define HD     64
#define MTOT   (NB * SEQ)
#define QK_SCALE_LOG2E 0.180336880111120f   // 0.125 * log2(e)

typedef __nv_bfloat16 bf16;

__device__ bf16 g_Xh[MTOT * HIDDIM], g_Xl[MTOT * HIDDIM];
__device__ bf16 g_Wqh[HIDDIM * HIDDIM], g_Wql[HIDDIM * HIDDIM];
__device__ bf16 g_Wkvh[HIDDIM * 128],   g_Wkvl[HIDDIM * 128];   // [Wk|Wv]
__device__ bf16 g_Woh[HIDDIM * HIDDIM], g_Wol[HIDDIM * HIDDIM];
__device__ bf16 g_Qh[MTOT * HIDDIM], g_Ql[MTOT * HIDDIM];
__device__ bf16 g_KVh[MTOT * 128],   g_KVl[MTOT * 128];         // [K|V] per row
__device__ bf16 g_Ah[MTOT * HIDDIM], g_Al[MTOT * HIDDIM];

// ---------------- helpers ----------------
__device__ __forceinline__ uint32_t s2u(const void* p) {
    uint32_t a;
    asm("{ .reg .u64 t; cvta.to.shared.u64 t, %1; cvt.u32.u64 %0, t; }"
        : "=r"(a) : "l"(p));
    return a;
}
__device__ __forceinline__ void cpa16(uint32_t dst, const void* src) {
    asm volatile("cp.async.cg.shared.global [%0], [%1], 16;" :: "r"(dst), "l"(src));
}
#define CP_COMMIT() asm volatile("cp.async.commit_group;" ::: "memory")
#define CP_WAIT(n)  asm volatile("cp.async.wait_group %0;" :: "n"(n) : "memory")

__device__ __forceinline__ void ldm4(uint32_t* r, uint32_t a) {
    asm volatile("ldmatrix.sync.aligned.m8n8.x4.shared.b16 {%0,%1,%2,%3}, [%4];"
        : "=r"(r[0]), "=r"(r[1]), "=r"(r[2]), "=r"(r[3]) : "r"(a));
}
__device__ __forceinline__ void ldm4t(uint32_t* r, uint32_t a) {
    asm volatile("ldmatrix.sync.aligned.m8n8.x4.trans.shared.b16 {%0,%1,%2,%3}, [%4];"
        : "=r"(r[0]), "=r"(r[1]), "=r"(r[2]), "=r"(r[3]) : "r"(a));
}
__device__ __forceinline__ void mmabf(float* d, const uint32_t* a, const uint32_t* b) {
    asm volatile("mma.sync.aligned.m16n8k16.row.col.f32.bf16.bf16.f32 "
        "{%0,%1,%2,%3},{%4,%5,%6,%7},{%8,%9},{%0,%1,%2,%3};"
        : "+f"(d[0]), "+f"(d[1]), "+f"(d[2]), "+f"(d[3])
        : "r"(a[0]), "r"(a[1]), "r"(a[2]), "r"(a[3]), "r"(b[0]), "r"(b[1]));
}

// single-MUFU exp2
__device__ __forceinline__ float ex2(float x) {
    float y;
    asm("ex2.approx.f32 %0, %1;" : "=f"(y) : "f"(x));
    return y;
}

// split pair (a,b) into packed bf16 hi/lo: 2 CVT + SHF + LOP + 2 FADD.
// Packing convention: low 16 bits = a, high 16 bits = b (same as before).
__device__ __forceinline__ void split2pk(float a, float b, uint32_t& hi, uint32_t& lo) {
    uint32_t h;
    asm("cvt.rn.satfinite.bf16x2.f32 %0, %1, %2;" : "=r"(h) : "f"(b), "f"(a));
    float ha = __uint_as_float(h << 16);
    float hb = __uint_as_float(h & 0xFFFF0000u);
    float la = a - ha;
    float lb = b - hb;
    asm("cvt.rn.satfinite.bf16x2.f32 %0, %1, %2;" : "=r"(lo) : "f"(lb), "f"(la));
    hi = h;
}

// ---------------------------------------------------------------------------
// Fused split. Wk/Wv interleave into the [1024 x 128] fused KV weight.
// ---------------------------------------------------------------------------
#define R_X  1048576
#define R_WQ (R_X + 262144)
#define R_WK (R_WQ + 16384)
#define R_WV (R_WK + 16384)
#define R_WO (R_WV + 262144)

__global__ void split_all(const float* __restrict__ x,  const float* __restrict__ wq,
                          const float* __restrict__ wk, const float* __restrict__ wv,
                          const float* __restrict__ wo,
                          bf16* xh, bf16* xl, bf16* qh, bf16* ql,
                          bf16* kvh, bf16* kvl, bf16* oh, bf16* ol)
{
    int i = blockIdx.x * blockDim.x + threadIdx.x;
    if (i >= R_WO) return;
    const float* in; bf16 *hi, *lo; int j, o4;
    if (i < R_X)       { in = x;  hi = xh; lo = xl; j = i;        o4 = j; }
    else if (i < R_WQ) { in = wq; hi = qh; lo = ql; j = i - R_X;  o4 = j; }
    else if (i < R_WK) { in = wk; hi = kvh; lo = kvl; j = i - R_WQ;
                         o4 = ((j >> 4) << 5) + (j & 15); }
    else if (i < R_WV) { in = wv; hi = kvh; lo = kvl; j = i - R_WK;
                         o4 = ((j >> 4) << 5) + (j & 15) + 16; }
    else               { in = wo; hi = oh; lo = ol; j = i - R_WV; o4 = j; }
    float4 v = ((const float4*)in)[j];
    uint32_t h0, l0, h1, l1;
    split2pk(v.x, v.y, h0, l0);
    split2pk(v.z, v.w, h1, l1);
    ((uint2*)hi)[o4] = make_uint2(h0, h1);
    ((uint2*)lo)[o4] = make_uint2(l0, l1);
}

// ---------------------------------------------------------------------------
// GEMM body: 3-stage cp.async pipeline, ONE __syncthreads per k-chunk.
// ---------------------------------------------------------------------------
template<int NTILE, int EPI>
__device__ __forceinline__
void gemm_body(const bf16* __restrict__ Ah, const bf16* __restrict__ Al,
               const bf16* __restrict__ Bh, const bf16* __restrict__ Bl,
               float* __restrict__ Cf, bf16* __restrict__ Ch, bf16* __restrict__ Cl,
               int N, int K, float scale, int m0, int n0, char* smc)
{
    constexpr int ASZ = 128 * 64;
    constexpr int BSZ = 32 * NTILE * 2;
    constexpr int STG = 2 * ASZ + 2 * BSZ;
    constexpr int RB  = NTILE * 2;
    constexpr int NTT = NTILE / 32;

    const int tid = threadIdx.x, l = tid & 31, wid = tid >> 5;
    const int wm = (wid & 1) * 64, wn = (wid >> 1) * (NTILE / 4);
    const uint32_t sb = s2u(smc);

    float acc[4][NTT][4];
    #pragma unroll
    for (int i = 0; i < 4; i++)
        #pragma unroll
        for (int j = 0; j < NTT; j++)
            #pragma unroll
            for (int k = 0; k < 4; k++) acc[i][j][k] = 0.0f;

    auto load_chunk = [&](int kc, int s) {
        uint32_t st = sb + (uint32_t)s * STG;
        #pragma unroll
        for (int i = 0; i < 2; i++) {
            int idx = tid + 256 * i;
            int r = idx >> 2, cq = idx & 3;
            uint32_t off = r * 64 + ((cq * 16) ^ ((r & 3) << 4));
            size_t src = (size_t)(m0 + r) * K + kc * 32 + cq * 8;
            cpa16(st + off, Ah + src);
            cpa16(st + ASZ + off, Al + src);
        }
        constexpr int BCH = BSZ / 16;
        constexpr int CPR = NTILE / 8;
        #pragma unroll
        for (int i = 0; i < (BCH + 255) / 256; i++) {
            int idx = tid + 256 * i;
            if (BCH < 256 || idx < BCH) {
                int r = idx / CPR, cq = idx % CPR;
                uint32_t off = 2 * ASZ + r * RB + ((cq * 16) ^ ((r & 7) << 4));
                size_t src = (size_t)(kc * 32 + r) * N + n0 + cq * 8;
                cpa16(st + off, Bh + src);
                cpa16(st + BSZ + off, Bl + src);
            }
        }
    };

    load_chunk(0, 0); CP_COMMIT();
    load_chunk(1, 1); CP_COMMIT();

    const int NC = K / 32;
    for (int kc = 0; kc < NC; kc++) {
        if (kc + 1 < NC) { CP_WAIT(1); } else { CP_WAIT(0); }
        __syncthreads();
        if (kc + 2 < NC) { load_chunk(kc + 2, (kc + 2) % 3); CP_COMMIT(); }

        uint32_t st = sb + (uint32_t)(kc % 3) * STG;
        #pragma unroll
        for (int ks = 0; ks < 2; ks++) {
            uint32_t af[2][4][4], bfr[2][NTT][2];
            #pragma unroll
            for (int mt = 0; mt < 4; mt++) {
                int row = wm + mt * 16 + (l & 15);
                uint32_t off = row * 64 + (((uint32_t)(ks * 32 + (l >> 4) * 16)) ^ ((row & 3) << 4));
                ldm4(af[0][mt], st + off);
                ldm4(af[1][mt], st + ASZ + off);
            }
            #pragma unroll
            for (int bg = 0; bg < NTT / 2; bg++) {
                int k = ks * 16 + (l & 7) + (((l >> 3) & 1) << 3);
                uint32_t byt = (uint32_t)((wn + bg * 16) * 2 + ((l >> 4) << 4));
                uint32_t off = 2 * ASZ + k * RB + (byt ^ ((k & 7) << 4));
                uint32_t t0[4], t1[4];
                ldm4t(t0, st + off);
                ldm4t(t1, st + BSZ + off);
                bfr[0][2*bg][0] = t0[0]; bfr[0][2*bg][1] = t0[1];
                bfr[0][2*bg+1][0] = t0[2]; bfr[0][2*bg+1][1] = t0[3];
                bfr[1][2*bg][0] = t1[0]; bfr[1][2*bg][1] = t1[1];
                bfr[1][2*bg+1][0] = t1[2]; bfr[1][2*bg+1][1] = t1[3];
            }
            #pragma unroll
            for (int mt = 0; mt < 4; mt++)
                #pragma unroll
                for (int nt = 0; nt < NTT; nt++) {
                    mmabf(acc[mt][nt], af[0][mt], bfr[0][nt]);
                    mmabf(acc[mt][nt], af[0][mt], bfr[1][nt]);
                    mmabf(acc[mt][nt], af[1][mt], bfr[0][nt]);
                }
        }
    }

    #pragma unroll
    for (int mt = 0; mt < 4; mt++)
        #pragma unroll
        for (int nt = 0; nt < NTT; nt++) {
            int rg = m0 + wm + mt * 16 + (l >> 2);
            int cg = n0 + wn + nt * 8 + (l & 3) * 2;
            if (EPI == 0) {
                *(float2*)(Cf + (size_t)rg * N + cg)       = make_float2(acc[mt][nt][0], acc[mt][nt][1]);
                *(float2*)(Cf + (size_t)(rg + 8) * N + cg) = make_float2(acc[mt][nt][2], acc[mt][nt][3]);
            } else {
                uint32_t h0, l0, h1, l1;
                split2pk(acc[mt][nt][0] * scale, acc[mt][nt][1] * scale, h0, l0);
                split2pk(acc[mt][nt][2] * scale, acc[mt][nt][3] * scale, h1, l1);
                ((uint32_t*)Ch)[((size_t)rg * N + cg) >> 1] = h0;
                ((uint32_t*)Cl)[((size_t)rg * N + cg) >> 1] = l0;
                ((uint32_t*)Ch)[((size_t)(rg + 8) * N + cg) >> 1] = h1;
                ((uint32_t*)Cl)[((size_t)(rg + 8) * N + cg) >> 1] = l1;
            }
        }
}

// Merged Q + fused-KV projection: grid (9, 32) = 288 CTAs (single wave).
__global__ __launch_bounds__(256, 2)
void qkv_proj(const bf16* __restrict__ Xh, const bf16* __restrict__ Xl,
              const bf16* __restrict__ Wqh, const bf16* __restrict__ Wql,
              const bf16* __restrict__ Wkvh, const bf16* __restrict__ Wkvl,
              bf16* Qh, bf16* Ql, bf16* KVh, bf16* KVl)
{
    extern __shared__ char smc[];
    const int bx = blockIdx.x, m0 = blockIdx.y * 128;
    if (bx < 8) {
        gemm_body<128, 1>(Xh, Xl, Wqh, Wql, nullptr, Qh, Ql,
                          HIDDIM, HIDDIM, QK_SCALE_LOG2E, m0, bx * 128, smc);
    } else {
        gemm_body<128, 1>(Xh, Xl, Wkvh, Wkvl, nullptr, KVh, KVl,
                          128, HIDDIM, 1.0f, m0, 0, smc);
    }
}

__global__ __launch_bounds__(256, 2)
void o_proj(const bf16* __restrict__ Ahp, const bf16* __restrict__ Alp,
            const bf16* __restrict__ Woh, const bf16* __restrict__ Wol,
            float* __restrict__ out)
{
    extern __shared__ char smc[];
    gemm_body<128, 0>(Ahp, Alp, Woh, Wol, out, nullptr, nullptr,
                      HIDDIM, HIDDIM, 1.0f, blockIdx.y * 128, blockIdx.x * 128, smc);
}

// ---------------------------------------------------------------------------
// Flash attention: 3-stage KV pipeline (stage 2 reuses dead Q smem).
// ---------------------------------------------------------------------------
#define FSMEM 196608
#define QT    256
#define NTKV  16

__device__ __forceinline__ uint32_t kv_stage_off(int m3) {
    return (m3 == 0) ? 65536u : ((m3 == 1) ? 131072u : 0u);
}

__global__ __launch_bounds__(512, 1)
void flash_bf(const bf16* __restrict__ Qh, const bf16* __restrict__ Ql,
              const bf16* __restrict__ KVh, const bf16* __restrict__ KVl,
              bf16* __restrict__ Ahg, bf16* __restrict__ Alg)
{
    extern __shared__ char smc[];
    const uint32_t sb = s2u(smc);

    const int tid = threadIdx.x, l = tid & 31, wid = tid >> 5;
    const int q0 = blockIdx.x * QT, h = blockIdx.y, b = blockIdx.z;

    auto load_kv = [&](int t, uint32_t stoff) {
        uint32_t st = sb + stoff;
        #pragma unroll
        for (int i = 0; i < 2; i++) {
            int idx = tid + 512 * i;
            int r = idx >> 3, cq = idx & 7;
            uint32_t off = r * 128 + ((cq * 16) ^ ((r & 7) << 4));
            size_t srcK = (size_t)(b * SEQ + t * 128 + r) * 128 + cq * 8;
            cpa16(st + off,         KVh + srcK);
            cpa16(st + 16384 + off, KVl + srcK);
            cpa16(st + 32768 + off, KVh + srcK + 64);
            cpa16(st + 49152 + off, KVl + srcK + 64);
        }
    };

    #pragma unroll
    for (int i = 0; i < 4; i++) {
        int idx = tid + 512 * i;
        int r = idx >> 3, cq = idx & 7;
        uint32_t off = r * 128 + ((cq * 16) ^ ((r & 7) << 4));
        size_t src = (size_t)(b * SEQ + q0 + r) * HIDDIM + h * HD + cq * 8;
        cpa16(sb + off,         Qh + src);
        cpa16(sb + 32768 + off, Ql + src);
    }
    load_kv(0, 65536u);
    CP_COMMIT();
    load_kv(1, 131072u);
    CP_COMMIT();

    uint32_t qf[2][4][4];
    float o[8][4];
    #pragma unroll
    for (int i = 0; i < 8; i++)
        #pragma unroll
        for (int k = 0; k < 4; k++) o[i][k] = 0.0f;
    float preg[2] = {0.0f, 0.0f};

    for (int t = 0; t < NTKV; t++) {
        if (t + 1 < NTKV) { CP_WAIT(1); } else { CP_WAIT(0); }
        __syncthreads();

        if (t == 0) {
            #pragma unroll
            for (int ks = 0; ks < 4; ks++) {
                int row = wid * 16 + (l & 15);
                uint32_t off = row * 128 + (((uint32_t)(ks * 32 + (l >> 4) * 16)) ^ ((row & 7) << 4));
                ldm4(qf[0][ks], sb + off);
                ldm4(qf[1][ks], sb + 32768 + off);
            }
            __syncthreads();
        }

        if (t + 2 < NTKV) { load_kv(t + 2, kv_stage_off((t + 2) % 3)); CP_COMMIT(); }

        const uint32_t stK = sb + kv_stage_off(t % 3);
        const uint32_t stV = stK + 32768;

        #pragma unroll
        for (int g = 0; g < 8; g++) {
            float sA[2][4], sB[2][4];
            #pragma unroll
            for (int i = 0; i < 2; i++)
                #pragma unroll
                for (int k = 0; k < 4; k++) { sA[i][k] = 0.0f; sB[i][k] = 0.0f; }

            int krow = g * 16 + (l & 7) + ((l >> 4) << 3);
            #pragma unroll
            for (int ks = 0; ks < 4; ks++) {
                uint32_t off = krow * 128 + (((uint32_t)(ks * 32 + ((l >> 3) & 1) * 16)) ^ ((krow & 7) << 4));
                uint32_t t0[4], t1[4];
                ldm4(t0, stK + off);
                ldm4(t1, stK + 16384 + off);
                uint32_t bh0[2] = {t0[0], t0[1]}, bh1[2] = {t0[2], t0[3]};
                uint32_t bl0[2] = {t1[0], t1[1]}, bl1[2] = {t1[2], t1[3]};
                mmabf(sA[0], qf[0][ks], bh0);
                mmabf(sB[0], qf[0][ks], bl0);
                mmabf(sA[1], qf[0][ks], bh1);
                mmabf(sB[1], qf[0][ks], bl1);
                mmabf(sA[0], qf[1][ks], bh0);
                mmabf(sA[1], qf[1][ks], bh1);
            }

            float s2[2][4];
            #pragma unroll
            for (int i = 0; i < 2; i++) {
                #pragma unroll
                for (int k = 0; k < 4; k++)
                    s2[i][k] = ex2(sA[i][k] + sB[i][k]);
                preg[0] += s2[i][0] + s2[i][1];
                preg[1] += s2[i][2] + s2[i][3];
            }

            uint32_t aH[4], aL[4];
            split2pk(s2[0][0], s2[0][1], aH[0], aL[0]);
            split2pk(s2[0][2], s2[0][3], aH[1], aL[1]);
            split2pk(s2[1][0], s2[1][1], aH[2], aL[2]);
            split2pk(s2[1][2], s2[1][3], aH[3], aL[3]);

            int key = g * 16 + (l & 7) + (((l >> 3) & 1) << 3);
            #pragma unroll
            for (int bg = 0; bg < 4; bg++) {
                uint32_t byt = (uint32_t)(bg * 32 + ((l >> 4) << 4));
                uint32_t off = key * 128 + (byt ^ ((key & 7) << 4));
                uint32_t t0[4], t1[4];
                ldm4t(t0, stV + off);
                ldm4t(t1, stV + 16384 + off);
                uint32_t bh0[2] = {t0[0], t0[1]}, bh1[2] = {t0[2], t0[3]};
                uint32_t bl0[2] = {t1[0], t1[1]}, bl1[2] = {t1[2], t1[3]};
                mmabf(o[2*bg],   aH, bh0);
                mmabf(o[2*bg],   aH, bl0);
                mmabf(o[2*bg],   aL, bh0);
                mmabf(o[2*bg+1], aH, bh1);
                mmabf(o[2*bg+1], aH, bl1);
                mmabf(o[2*bg+1], aL, bh1);
            }
        }
    }

    #pragma unroll
    for (int i = 0; i < 2; i++) {
        preg[i] += __shfl_xor_sync(0xffffffffu, preg[i], 1);
        preg[i] += __shfl_xor_sync(0xffffffffu, preg[i], 2);
    }
    float inv0 = 1.0f / preg[0], inv1 = 1.0f / preg[1];

    int r0 = wid * 16 + (l >> 2);
    size_t base0 = (size_t)(b * SEQ + q0 + r0) * HIDDIM + h * HD;
    size_t base1 = (size_t)(b * SEQ + q0 + r0 + 8) * HIDDIM + h * HD;
    #pragma unroll
    for (int nt = 0; nt < 8; nt++) {
        int col = nt * 8 + (l & 3) * 2;
        uint32_t hi, lo;
        split2pk(o[nt][0] * inv0, o[nt][1] * inv0, hi, lo);
        ((uint32_t*)Ahg)[(base0 + col) >> 1] = hi;
        ((uint32_t*)Alg)[(base0 + col) >> 1] = lo;
        split2pk(o[nt][2] * inv1, o[nt][3] * inv1, hi, lo);
        ((uint32_t*)Ahg)[(base1 + col) >> 1] = hi;
        ((uint32_t*)Alg)[(base1 + col) >> 1] = lo;
    }
}

// ---------------------------------------------------------------------------
extern "C" void kernel_launch(void* const* d_in, const int* in_sizes, int n_in,
                              void* d_out, int out_size)
{
    const float* hs = (const float*)d_in[0];
    const float* Wq = (const float*)d_in[1];
    const float* Wk = (const float*)d_in[2];
    const float* Wv = (const float*)d_in[3];
    const float* Wo = (const float*)d_in[4];
    float* out = (float*)d_out;

    bf16 *Xh, *Xl, *Wqh, *Wql, *Wkvh, *Wkvl, *Woh, *Wol;
    bf16 *Qh, *Ql, *KVh, *KVl, *Ahp, *Alp;
    cudaGetSymbolAddress((void**)&Xh, g_Xh);     cudaGetSymbolAddress((void**)&Xl, g_Xl);
    cudaGetSymbolAddress((void**)&Wqh, g_Wqh);   cudaGetSymbolAddress((void**)&Wql, g_Wql);
    cudaGetSymbolAddress((void**)&Wkvh, g_Wkvh); cudaGetSymbolAddress((void**)&Wkvl, g_Wkvl);
    cudaGetSymbolAddress((void**)&Woh, g_Woh);   cudaGetSymbolAddress((void**)&Wol, g_Wol);
    cudaGetSymbolAddress((void**)&Qh, g_Qh);     cudaGetSymbolAddress((void**)&Ql, g_Ql);
    cudaGetSymbolAddress((void**)&KVh, g_KVh);   cudaGetSymbolAddress((void**)&KVl, g_KVl);
    cudaGetSymbolAddress((void**)&Ahp, g_Ah);    cudaGetSymbolAddress((void**)&Alp, g_Al);

    constexpr int STG128 = 2 * (128 * 64) + 2 * (32 * 128 * 2);  // 32768 per stage
    cudaFuncSetAttribute(qkv_proj, cudaFuncAttributeMaxDynamicSharedMemorySize, 3 * STG128);
    cudaFuncSetAttribute(o_proj,   cudaFuncAttributeMaxDynamicSharedMemorySize, 3 * STG128);
    cudaFuncSetAttribute(flash_bf, cudaFuncAttributeMaxDynamicSharedMemorySize, FSMEM);

    split_all<<<(R_WO + 255) / 256, 256>>>(hs, Wq, Wk, Wv, Wo,
                                           Xh, Xl, Wqh, Wql, Wkvh, Wkvl, Woh, Wol);
    qkv_proj<<<dim3(9, MTOT / 128), 256, 3 * STG128>>>(
        Xh, Xl, Wqh, Wql, Wkvh, Wkvl, Qh, Ql, KVh, KVl);
    flash_bf<<<dim3(SEQ / QT, NHEAD, NB), 512, FSMEM>>>(Qh, Ql, KVh, KVl, Ahp, Alp);
    o_proj<<<dim3(HIDDIM / 128, MTOT / 128), 256, 3 * STG128>>>(Ahp, Alp, Woh, Wol, out);
}

// round 14
// speedup vs baseline: 3.9753x; 2.3223x over previous
#include <cuda_runtime.h>
#include <cuda_fp16.h>
#include <cstdint>

// ---------------------------------------------------------------------------
// MQA, pure-fp16 mma.sync (f32 accumulate). R14: single-product fp16 replaces
// 3-product split-bf16 (fp16 roundoff 2^-12 keeps rel_err ~3-6e-4 < 1e-3).
// Structure identical to R13: 3-stage cp.async pipelines, fused KV, exp2.
// ---------------------------------------------------------------------------
#define NB     2
#define SEQ    2048
#define HIDDIM 1024
#define NHEAD  16
#define HD     64
#define MTOT   (NB * SEQ)
#define QK_SCALE_LOG2E 0.180336880111120f   // 0.125 * log2(e)

typedef __half fp16;

__device__ fp16 g_X16[MTOT * HIDDIM];
__device__ fp16 g_Wq16[HIDDIM * HIDDIM];
__device__ fp16 g_Wkv16[HIDDIM * 128];     // [Wk|Wv]
__device__ fp16 g_Wo16[HIDDIM * HIDDIM];
__device__ fp16 g_Q16[MTOT * HIDDIM];
__device__ fp16 g_KV16[MTOT * 128];        // [K|V] per row
__device__ fp16 g_A16[MTOT * HIDDIM];

// ---------------- helpers ----------------
__device__ __forceinline__ uint32_t s2u(const void* p) {
    uint32_t a;
    asm("{ .reg .u64 t; cvta.to.shared.u64 t, %1; cvt.u32.u64 %0, t; }"
        : "=r"(a) : "l"(p));
    return a;
}
__device__ __forceinline__ void cpa16(uint32_t dst, const void* src) {
    asm volatile("cp.async.cg.shared.global [%0], [%1], 16;" :: "r"(dst), "l"(src));
}
#define CP_COMMIT() asm volatile("cp.async.commit_group;" ::: "memory")
#define CP_WAIT(n)  asm volatile("cp.async.wait_group %0;" :: "n"(n) : "memory")

__device__ __forceinline__ void ldm4(uint32_t* r, uint32_t a) {
    asm volatile("ldmatrix.sync.aligned.m8n8.x4.shared.b16 {%0,%1,%2,%3}, [%4];"
        : "=r"(r[0]), "=r"(r[1]), "=r"(r[2]), "=r"(r[3]) : "r"(a));
}
__device__ __forceinline__ void ldm4t(uint32_t* r, uint32_t a) {
    asm volatile("ldmatrix.sync.aligned.m8n8.x4.trans.shared.b16 {%0,%1,%2,%3}, [%4];"
        : "=r"(r[0]), "=r"(r[1]), "=r"(r[2]), "=r"(r[3]) : "r"(a));
}
__device__ __forceinline__ void mmah(float* d, const uint32_t* a, const uint32_t* b) {
    asm volatile("mma.sync.aligned.m16n8k16.row.col.f32.f16.f16.f32 "
        "{%0,%1,%2,%3},{%4,%5,%6,%7},{%8,%9},{%0,%1,%2,%3};"
        : "+f"(d[0]), "+f"(d[1]), "+f"(d[2]), "+f"(d[3])
        : "r"(a[0]), "r"(a[1]), "r"(a[2]), "r"(a[3]), "r"(b[0]), "r"(b[1]));
}
// single-MUFU exp2
__device__ __forceinline__ float ex2(float x) {
    float y;
    asm("ex2.approx.f32 %0, %1;" : "=f"(y) : "f"(x));
    return y;
}
// pack two floats -> fp16x2 (low half = a)
__device__ __forceinline__ uint32_t pk2h(float a, float b) {
    uint32_t r;
    asm("cvt.rn.f16x2.f32 %0, %1, %2;" : "=r"(r) : "f"(b), "f"(a));
    return r;
}

// ---------------------------------------------------------------------------
// Fused cast: all 5 fp32 inputs -> fp16 (Wk/Wv interleave into [1024 x 128]).
// Region boundaries in float4 units.
// ---------------------------------------------------------------------------
#define R_X  1048576
#define R_WQ (R_X + 262144)
#define R_WK (R_WQ + 16384)
#define R_WV (R_WK + 16384)
#define R_WO (R_WV + 262144)

__global__ void cast_all(const float* __restrict__ x,  const float* __restrict__ wq,
                         const float* __restrict__ wk, const float* __restrict__ wv,
                         const float* __restrict__ wo,
                         fp16* xo, fp16* qo, fp16* kvo, fp16* oo)
{
    int i = blockIdx.x * blockDim.x + threadIdx.x;
    if (i >= R_WO) return;
    const float* in; fp16* dst; int j, o4;
    if (i < R_X)       { in = x;  dst = xo; j = i;        o4 = j; }
    else if (i < R_WQ) { in = wq; dst = qo; j = i - R_X;  o4 = j; }
    else if (i < R_WK) { in = wk; dst = kvo; j = i - R_WQ;
                         o4 = ((j >> 4) << 5) + (j & 15); }
    else if (i < R_WV) { in = wv; dst = kvo; j = i - R_WK;
                         o4 = ((j >> 4) << 5) + (j & 15) + 16; }
    else               { in = wo; dst = oo; j = i - R_WV; o4 = j; }
    float4 v = ((const float4*)in)[j];
    ((uint2*)dst)[o4] = make_uint2(pk2h(v.x, v.y), pk2h(v.z, v.w));
}

// ---------------------------------------------------------------------------
// GEMM body: C[128 x NTILE] tile of A[M,K]*B[K,N]; fp16 in, 3-stage cp.async,
// one __syncthreads per k-chunk.
// ---------------------------------------------------------------------------
template<int NTILE, int EPI>
__device__ __forceinline__
void gemm_body(const fp16* __restrict__ A, const fp16* __restrict__ B,
               float* __restrict__ Cf, fp16* __restrict__ Ch,
               int N, int K, float scale, int m0, int n0, char* smc)
{
    constexpr int ASZ = 128 * 64;        // 128 rows x 32 fp16 = 8KB
    constexpr int BSZ = 32 * NTILE * 2;  // fp16
    constexpr int STG = ASZ + BSZ;
    constexpr int RB  = NTILE * 2;
    constexpr int NTT = NTILE / 32;

    const int tid = threadIdx.x, l = tid & 31, wid = tid >> 5;
    const int wm = (wid & 1) * 64, wn = (wid >> 1) * (NTILE / 4);
    const uint32_t sb = s2u(smc);

    float acc[4][NTT][4];
    #pragma unroll
    for (int i = 0; i < 4; i++)
        #pragma unroll
        for (int j = 0; j < NTT; j++)
            #pragma unroll
            for (int k = 0; k < 4; k++) acc[i][j][k] = 0.0f;

    auto load_chunk = [&](int kc, int s) {
        uint32_t st = sb + (uint32_t)s * STG;
        #pragma unroll
        for (int i = 0; i < 2; i++) {           // A: 512 16B-chunks
            int idx = tid + 256 * i;
            int r = idx >> 2, cq = idx & 3;
            uint32_t off = r * 64 + ((cq * 16) ^ ((r & 3) << 4));
            size_t src = (size_t)(m0 + r) * K + kc * 32 + cq * 8;
            cpa16(st + off, A + src);
        }
        constexpr int BCH = BSZ / 16;
        constexpr int CPR = NTILE / 8;
        #pragma unroll
        for (int i = 0; i < (BCH + 255) / 256; i++) {
            int idx = tid + 256 * i;
            if (BCH < 256 || idx < BCH) {
                int r = idx / CPR, cq = idx % CPR;
                uint32_t off = ASZ + r * RB + ((cq * 16) ^ ((r & 7) << 4));
                size_t src = (size_t)(kc * 32 + r) * N + n0 + cq * 8;
                cpa16(st + off, B + src);
            }
        }
    };

    load_chunk(0, 0); CP_COMMIT();
    load_chunk(1, 1); CP_COMMIT();

    const int NC = K / 32;
    for (int kc = 0; kc < NC; kc++) {
        if (kc + 1 < NC) { CP_WAIT(1); } else { CP_WAIT(0); }
        __syncthreads();
        if (kc + 2 < NC) { load_chunk(kc + 2, (kc + 2) % 3); CP_COMMIT(); }

        uint32_t st = sb + (uint32_t)(kc % 3) * STG;
        #pragma unroll
        for (int ks = 0; ks < 2; ks++) {
            uint32_t af[4][4], bfr[NTT][2];
            #pragma unroll
            for (int mt = 0; mt < 4; mt++) {
                int row = wm + mt * 16 + (l & 15);
                uint32_t off = row * 64 + (((uint32_t)(ks * 32 + (l >> 4) * 16)) ^ ((row & 3) << 4));
                ldm4(af[mt], st + off);
            }
            #pragma unroll
            for (int bg = 0; bg < NTT / 2; bg++) {
                int k = ks * 16 + (l & 7) + (((l >> 3) & 1) << 3);
                uint32_t byt = (uint32_t)((wn + bg * 16) * 2 + ((l >> 4) << 4));
                uint32_t off = ASZ + k * RB + (byt ^ ((k & 7) << 4));
                uint32_t t0[4];
                ldm4t(t0, st + off);
                bfr[2*bg][0] = t0[0]; bfr[2*bg][1] = t0[1];
                bfr[2*bg+1][0] = t0[2]; bfr[2*bg+1][1] = t0[3];
            }
            #pragma unroll
            for (int mt = 0; mt < 4; mt++)
                #pragma unroll
                for (int nt = 0; nt < NTT; nt++)
                    mmah(acc[mt][nt], af[mt], bfr[nt]);
        }
    }

    #pragma unroll
    for (int mt = 0; mt < 4; mt++)
        #pragma unroll
        for (int nt = 0; nt < NTT; nt++) {
            int rg = m0 + wm + mt * 16 + (l >> 2);
            int cg = n0 + wn + nt * 8 + (l & 3) * 2;
            if (EPI == 0) {
                *(float2*)(Cf + (size_t)rg * N + cg)       = make_float2(acc[mt][nt][0], acc[mt][nt][1]);
                *(float2*)(Cf + (size_t)(rg + 8) * N + cg) = make_float2(acc[mt][nt][2], acc[mt][nt][3]);
            } else {
                ((uint32_t*)Ch)[((size_t)rg * N + cg) >> 1] =
                    pk2h(acc[mt][nt][0] * scale, acc[mt][nt][1] * scale);
                ((uint32_t*)Ch)[((size_t)(rg + 8) * N + cg) >> 1] =
                    pk2h(acc[mt][nt][2] * scale, acc[mt][nt][3] * scale);
            }
        }
}

// Merged Q + fused-KV projection: grid (9, 32) = 288 CTAs (single wave).
__global__ __launch_bounds__(256, 2)
void qkv_proj(const fp16* __restrict__ X, const fp16* __restrict__ Wq,
              const fp16* __restrict__ Wkv, fp16* Q, fp16* KV)
{
    extern __shared__ char smc[];
    const int bx = blockIdx.x, m0 = blockIdx.y * 128;
    if (bx < 8) {
        gemm_body<128, 1>(X, Wq, nullptr, Q, HIDDIM, HIDDIM, QK_SCALE_LOG2E, m0, bx * 128, smc);
    } else {
        gemm_body<128, 1>(X, Wkv, nullptr, KV, 128, HIDDIM, 1.0f, m0, 0, smc);
    }
}

__global__ __launch_bounds__(256, 2)
void o_proj(const fp16* __restrict__ Ap, const fp16* __restrict__ Wo,
            float* __restrict__ out)
{
    extern __shared__ char smc[];
    gemm_body<128, 0>(Ap, Wo, out, nullptr, HIDDIM, HIDDIM, 1.0f,
                      blockIdx.y * 128, blockIdx.x * 128, smc);
}

// ---------------------------------------------------------------------------
// Flash attention, pure fp16, 3-stage KV pipeline (stage 2 reuses dead Q smem).
// smem: [0,32K) Q (-> stage2) | [32K,64K) stage0 | [64K,96K) stage1.
// Stage layout: K tile 16K at +0, V tile 16K at +16384.
// ---------------------------------------------------------------------------
#define FSMEM 98304
#define QT    256
#define NTKV  16

__device__ __forceinline__ uint32_t kv_stage_off(int m3) {
    return (m3 == 0) ? 32768u : ((m3 == 1) ? 65536u : 0u);
}

__global__ __launch_bounds__(512, 1)
void flash_h(const fp16* __restrict__ Q, const fp16* __restrict__ KV,
             fp16* __restrict__ Ag)
{
    extern __shared__ char smc[];
    const uint32_t sb = s2u(smc);

    const int tid = threadIdx.x, l = tid & 31, wid = tid >> 5;
    const int q0 = blockIdx.x * QT, h = blockIdx.y, b = blockIdx.z;

    auto load_kv = [&](int t, uint32_t stoff) {
        uint32_t st = sb + stoff;
        #pragma unroll
        for (int i = 0; i < 2; i++) {          // K then V via +64 col
            int idx = tid + 512 * i;           // 1024 chunks each
            int r = idx >> 3, cq = idx & 7;
            uint32_t off = r * 128 + ((cq * 16) ^ ((r & 7) << 4));
            size_t srcK = (size_t)(b * SEQ + t * 128 + r) * 128 + cq * 8;
            cpa16(st + off,         KV + srcK);
            cpa16(st + 16384 + off, KV + srcK + 64);
        }
    };

    // prologue: Q tile (2048 chunks) + KV tiles 0,1
    #pragma unroll
    for (int i = 0; i < 4; i++) {
        int idx = tid + 512 * i;
        int r = idx >> 3, cq = idx & 7;
        uint32_t off = r * 128 + ((cq * 16) ^ ((r & 7) << 4));
        size_t src = (size_t)(b * SEQ + q0 + r) * HIDDIM + h * HD + cq * 8;
        cpa16(sb + off, Q + src);
    }
    load_kv(0, 32768u);
    CP_COMMIT();
    load_kv(1, 65536u);
    CP_COMMIT();

    uint32_t qf[4][4];
    float o[8][4];
    #pragma unroll
    for (int i = 0; i < 8; i++)
        #pragma unroll
        for (int k = 0; k < 4; k++) o[i][k] = 0.0f;
    float preg[2] = {0.0f, 0.0f};

    for (int t = 0; t < NTKV; t++) {
        if (t + 1 < NTKV) { CP_WAIT(1); } else { CP_WAIT(0); }
        __syncthreads();

        if (t == 0) {       // Q fragments once; Q smem then becomes stage 2
            #pragma unroll
            for (int ks = 0; ks < 4; ks++) {
                int row = wid * 16 + (l & 15);
                uint32_t off = row * 128 + (((uint32_t)(ks * 32 + (l >> 4) * 16)) ^ ((row & 7) << 4));
                ldm4(qf[ks], sb + off);
            }
            __syncthreads();
        }

        if (t + 2 < NTKV) { load_kv(t + 2, kv_stage_off((t + 2) % 3)); CP_COMMIT(); }

        const uint32_t stK = sb + kv_stage_off(t % 3);
        const uint32_t stV = stK + 16384;

        #pragma unroll
        for (int g = 0; g < 8; g++) {
            float sA[2][4];
            #pragma unroll
            for (int i = 0; i < 2; i++)
                #pragma unroll
                for (int k = 0; k < 4; k++) sA[i][k] = 0.0f;

            int krow = g * 16 + (l & 7) + ((l >> 4) << 3);
            #pragma unroll
            for (int ks = 0; ks < 4; ks++) {
                uint32_t off = krow * 128 + (((uint32_t)(ks * 32 + ((l >> 3) & 1) * 16)) ^ ((krow & 7) << 4));
                uint32_t t0[4];
                ldm4(t0, stK + off);
                uint32_t bh0[2] = {t0[0], t0[1]}, bh1[2] = {t0[2], t0[3]};
                mmah(sA[0], qf[ks], bh0);
                mmah(sA[1], qf[ks], bh1);
            }

            float s2[2][4];
            #pragma unroll
            for (int i = 0; i < 2; i++) {
                #pragma unroll
                for (int k = 0; k < 4; k++)
                    s2[i][k] = ex2(sA[i][k]);
                preg[0] += s2[i][0] + s2[i][1];
                preg[1] += s2[i][2] + s2[i][3];
            }

            uint32_t aH[4];
            aH[0] = pk2h(s2[0][0], s2[0][1]);
            aH[1] = pk2h(s2[0][2], s2[0][3]);
            aH[2] = pk2h(s2[1][0], s2[1][1]);
            aH[3] = pk2h(s2[1][2], s2[1][3]);

            int key = g * 16 + (l & 7) + (((l >> 3) & 1) << 3);
            #pragma unroll
            for (int bg = 0; bg < 4; bg++) {
                uint32_t byt = (uint32_t)(bg * 32 + ((l >> 4) << 4));
                uint32_t off = key * 128 + (byt ^ ((key & 7) << 4));
                uint32_t t0[4];
                ldm4t(t0, stV + off);
                uint32_t bh0[2] = {t0[0], t0[1]}, bh1[2] = {t0[2], t0[3]};
                mmah(o[2*bg],   aH, bh0);
                mmah(o[2*bg+1], aH, bh1);
            }
        }
    }

    #pragma unroll
    for (int i = 0; i < 2; i++) {
        preg[i] += __shfl_xor_sync(0xffffffffu, preg[i], 1);
        preg[i] += __shfl_xor_sync(0xffffffffu, preg[i], 2);
    }
    float inv0 = 1.0f / preg[0], inv1 = 1.0f / preg[1];

    int r0 = wid * 16 + (l >> 2);
    size_t base0 = (size_t)(b * SEQ + q0 + r0) * HIDDIM + h * HD;
    size_t base1 = (size_t)(b * SEQ + q0 + r0 + 8) * HIDDIM + h * HD;
    #pragma unroll
    for (int nt = 0; nt < 8; nt++) {
        int col = nt * 8 + (l & 3) * 2;
        ((uint32_t*)Ag)[(base0 + col) >> 1] = pk2h(o[nt][0] * inv0, o[nt][1] * inv0);
        ((uint32_t*)Ag)[(base1 + col) >> 1] = pk2h(o[nt][2] * inv1, o[nt][3] * inv1);
    }
}

// ---------------------------------------------------------------------------
extern "C" void kernel_launch(void* const* d_in, const int* in_sizes, int n_in,
                              void* d_out, int out_size)
{
    const float* hs = (const float*)d_in[0];
    const float* Wq = (const float*)d_in[1];
    const float* Wk = (const float*)d_in[2];
    const float* Wv = (const float*)d_in[3];
    const float* Wo = (const float*)d_in[4];
    float* out = (float*)d_out;

    fp16 *X16, *Wq16, *Wkv16, *Wo16, *Q16, *KV16, *A16;
    cudaGetSymbolAddress((void**)&X16, g_X16);
    cudaGetSymbolAddress((void**)&Wq16, g_Wq16);
    cudaGetSymbolAddress((void**)&Wkv16, g_Wkv16);
    cudaGetSymbolAddress((void**)&Wo16, g_Wo16);
    cudaGetSymbolAddress((void**)&Q16, g_Q16);
    cudaGetSymbolAddress((void**)&KV16, g_KV16);
    cudaGetSymbolAddress((void**)&A16, g_A16);

    constexpr int STG128 = 128 * 64 + 32 * 128 * 2;   // 16384 per stage
    cudaFuncSetAttribute(qkv_proj, cudaFuncAttributeMaxDynamicSharedMemorySize, 3 * STG128);
    cudaFuncSetAttribute(o_proj,   cudaFuncAttributeMaxDynamicSharedMemorySize, 3 * STG128);
    cudaFuncSetAttribute(flash_h,  cudaFuncAttributeMaxDynamicSharedMemorySize, FSMEM);

    cast_all<<<(R_WO + 255) / 256, 256>>>(hs, Wq, Wk, Wv, Wo, X16, Wq16, Wkv16, Wo16);
    qkv_proj<<<dim3(9, MTOT / 128), 256, 3 * STG128>>>(X16, Wq16, Wkv16, Q16, KV16);
    flash_h<<<dim3(SEQ / QT, NHEAD, NB), 512, FSMEM>>>(Q16, KV16, A16);
    o_proj<<<dim3(HIDDIM / 128, MTOT / 128), 256, 3 * STG128>>>(A16, Wo16, out);
}